// round 3
// baseline (speedup 1.0000x reference)
#include <cuda_runtime.h>
#include <math.h>

#define NA   50000
#define NEg  200000
#define NSg  1000000
#define HIDF 128
#define OUTF 144

// Scratch (static device globals; no allocation allowed)
__device__ float g_PA[(size_t)NA * 256];        // per-atom: [f0|f1|s0|s1] each 64
__device__ float g_PE[(size_t)NEg * 128];       // per-edge: [f_e|s_e] each 64
__device__ float g_agg[(size_t)2 * NEg * 64];   // scatter target
__device__ float g_hid[(size_t)NEg * HIDF];     // stage-5 hidden

// ---------------------------------------------------------------------------
// f32x2 packed-math helpers (Blackwell FFMA2 path)
// ---------------------------------------------------------------------------
__device__ __forceinline__ unsigned long long pack2(float lo, float hi) {
    unsigned long long r;
    asm("mov.b64 %0, {%1, %2};" : "=l"(r) : "f"(lo), "f"(hi));
    return r;
}
__device__ __forceinline__ void unpack2(unsigned long long v, float& lo, float& hi) {
    asm("mov.b64 {%0, %1}, %2;" : "=f"(lo), "=f"(hi) : "l"(v));
}
__device__ __forceinline__ unsigned long long fma2(unsigned long long a,
                                                   unsigned long long b,
                                                   unsigned long long c) {
    unsigned long long d;
    asm("fma.rn.f32x2 %0, %1, %2, %3;" : "=l"(d) : "l"(a), "l"(b), "l"(c));
    return d;
}
// 16B shared load as two packed f32x2 (no pack instructions needed)
__device__ __forceinline__ void lds_v2u64(unsigned sa, unsigned long long& x0,
                                          unsigned long long& x1) {
    asm("ld.shared.v2.u64 {%0, %1}, [%2];" : "=l"(x0), "=l"(x1) : "r"(sa));
}

// ---------------------------------------------------------------------------
// Zero the scatter buffer
// ---------------------------------------------------------------------------
__global__ void kZero() {
    size_t i = (size_t)blockIdx.x * blockDim.x + threadIdx.x;
    size_t n4 = (size_t)2 * NEg * 64 / 4;
    if (i < n4) reinterpret_cast<float4*>(g_agg)[i] = make_float4(0.f, 0.f, 0.f, 0.f);
}

// ---------------------------------------------------------------------------
// Kernel A: per-atom projections
// ---------------------------------------------------------------------------
__global__ __launch_bounds__(256) void kA(const float* __restrict__ atom,
                                          const float* __restrict__ Wf,
                                          const float* __restrict__ Ws) {
    int t = threadIdx.x;
    int m = t >> 6;
    int c = t & 63;
    const float* W = ((m < 2) ? Wf : Ws) + (size_t)(m & 1) * 64 * 64;
    float w[64];
#pragma unroll
    for (int k = 0; k < 64; k++) w[k] = W[k * 64 + c];

    __shared__ float xs[32][64];
    int a0 = blockIdx.x * 32;
    for (int i = t; i < 32 * 64; i += 256) {
        int a = a0 + (i >> 6);
        xs[i >> 6][i & 63] = (a < NA) ? atom[(size_t)a * 64 + (i & 63)] : 0.f;
    }
    __syncthreads();

    for (int j = 0; j < 32; j++) {
        int a = a0 + j;
        if (a >= NA) break;
        const float4* x4 = reinterpret_cast<const float4*>(xs[j]);
        float acc = 0.f;
#pragma unroll
        for (int k4 = 0; k4 < 16; k4++) {
            float4 v = x4[k4];
            acc = fmaf(v.x, w[4 * k4 + 0], acc);
            acc = fmaf(v.y, w[4 * k4 + 1], acc);
            acc = fmaf(v.z, w[4 * k4 + 2], acc);
            acc = fmaf(v.w, w[4 * k4 + 3], acc);
        }
        g_PA[(size_t)a * 256 + t] = acc;
    }
}

// ---------------------------------------------------------------------------
// Kernel B: per-edge projections, f32x2 packed accumulation
// ---------------------------------------------------------------------------
__global__ __launch_bounds__(256) void kB(const float* __restrict__ ef,
                                          const float* __restrict__ Wf,
                                          const float* __restrict__ Ws) {
    extern __shared__ float smB[];
    float* Wc = smB;                 // [112][128]
    float* xs = smB + 112 * 128;     // [32][112]
    int t = threadIdx.x;

    for (int i = t; i < 112 * 128; i += 256) {
        int k = i >> 7, c = i & 127;
        Wc[i] = (c < 64) ? Wf[(size_t)(128 + k) * 64 + c]
                         : Ws[(size_t)(128 + k) * 64 + (c - 64)];
    }
    __syncthreads();

    int c = t & 127, g = t >> 7;
    unsigned xs_sa = (unsigned)__cvta_generic_to_shared(xs + (size_t)g * 16 * 112);
    const int ntiles = NEg / 32;   // 6250
    for (int tile = blockIdx.x; tile < ntiles; tile += gridDim.x) {
        int e0 = tile * 32;
        __syncthreads();
        for (int i = t; i < 32 * 112; i += 256) {
            int el = i / 112, k = i - el * 112;
            xs[i] = ef[(size_t)(e0 + el) * 112 + k];
        }
        __syncthreads();

        unsigned long long acc2[16];
#pragma unroll
        for (int e = 0; e < 16; e++) acc2[e] = 0ULL;

#pragma unroll 4
        for (int k4 = 0; k4 < 28; k4++) {
            float w0 = Wc[(4 * k4 + 0) * 128 + c];
            float w1 = Wc[(4 * k4 + 1) * 128 + c];
            float w2 = Wc[(4 * k4 + 2) * 128 + c];
            float w3 = Wc[(4 * k4 + 3) * 128 + c];
            unsigned long long wp01 = pack2(w0, w1);
            unsigned long long wp23 = pack2(w2, w3);
#pragma unroll
            for (int e = 0; e < 16; e++) {
                unsigned long long x01, x23;
                lds_v2u64(xs_sa + (unsigned)(e * 112 + 4 * k4) * 4, x01, x23);
                acc2[e] = fma2(x01, wp01, acc2[e]);
                acc2[e] = fma2(x23, wp23, acc2[e]);
            }
        }
#pragma unroll
        for (int e = 0; e < 16; e++) {
            float lo, hi;
            unpack2(acc2[e], lo, hi);
            g_PE[(size_t)(e0 + g * 16 + e) * 128 + c] = lo + hi;
        }
    }
}

// ---------------------------------------------------------------------------
// Kernel C: per-sub gather + gate + decay + atomic scatter.
// v3: two warps per row, one column per lane, weights in registers, no LDS.
// ---------------------------------------------------------------------------
__global__ __launch_bounds__(256) void kC(const int*   __restrict__ sai,
                                          const int*   __restrict__ sei,
                                          const float* __restrict__ ang,
                                          const int*   __restrict__ sidx,
                                          const float* __restrict__ dist,
                                          const float* __restrict__ Wf,
                                          const float* __restrict__ bf,
                                          const float* __restrict__ Ws,
                                          const float* __restrict__ bs) {
    int t = threadIdx.x;
    int lane = t & 31;
    unsigned u0 = ((unsigned)blockIdx.x * blockDim.x + t) >> 5;   // unit id
    unsigned nunits = ((unsigned)gridDim.x * blockDim.x) >> 5;

    // column handled by this lane depends on half = u&1, constant across the
    // grid-stride loop because nunits is even.
    int half = u0 & 1;
    int col = half * 32 + lane;

    float wfa[16], wsa[16];
#pragma unroll
    for (int k = 0; k < 16; k++) {
        wfa[k] = Wf[(size_t)(240 + k) * 64 + col];
        wsa[k] = Ws[(size_t)(240 + k) * 64 + col];
    }
    float bfv = bf[col];
    float bsv = bs[col];

    for (unsigned u = u0; u < 2u * NSg; u += nunits) {
        unsigned s = u >> 1;
        int i0 = sai[2 * s], i1 = sai[2 * s + 1];
        int e  = sei[s];
        int si = sidx[s];
        float d = dist[e];
        float decay = __expf(-d * d * (1.0f / 18.0f));

        const float4* ap = reinterpret_cast<const float4*>(ang + (size_t)s * 16);
        float4 a0 = ap[0], a1 = ap[1], a2 = ap[2], a3 = ap[3];
        float av[16] = {a0.x,a0.y,a0.z,a0.w, a1.x,a1.y,a1.z,a1.w,
                        a2.x,a2.y,a2.z,a2.w, a3.x,a3.y,a3.z,a3.w};

        const float* pa0 = g_PA + (size_t)i0 * 256;
        const float* pa1 = g_PA + (size_t)i1 * 256;
        const float* pe  = g_PE + (size_t)e  * 128;

        float vf = pa0[col] + pa1[64 + col] + pe[col] + bfv;
        float vs = pa0[128 + col] + pa1[192 + col] + pe[64 + col] + bsv;

#pragma unroll
        for (int k = 0; k < 16; k++) {
            vf = fmaf(av[k], wfa[k], vf);
            vs = fmaf(av[k], wsa[k], vs);
        }

        float sg = __fdividef(1.f, 1.f + __expf(-vf));
        float sp = fmaxf(vs, 0.f) + __logf(1.f + __expf(-fabsf(vs)));
        float o  = sg * sp * decay;

        atomicAdd(g_agg + (size_t)si * 64 + col, o);
    }
}

// ---------------------------------------------------------------------------
// Kernel D1: hid = silu([agg0|agg1|ef] @ W1 + b1), f32x2 packed
// ---------------------------------------------------------------------------
__global__ __launch_bounds__(256) void kD1(const float* __restrict__ ef,
                                           const float* __restrict__ W1,
                                           const float* __restrict__ b1) {
    extern __shared__ float smD1[];
    float* W1s = smD1;                 // [240][128]
    float* xs  = smD1 + 240 * 128;     // [32][240]
    int t = threadIdx.x;

    for (int i = t; i < 240 * 128; i += 256) W1s[i] = W1[i];
    __syncthreads();

    int c = t & 127, g = t >> 7;
    float bias = b1[c];
    unsigned xs_sa = (unsigned)__cvta_generic_to_shared(xs + (size_t)g * 16 * 240);
    const int ntiles = NEg / 32;
    for (int tile = blockIdx.x; tile < ntiles; tile += gridDim.x) {
        int e0 = tile * 32;
        __syncthreads();
        for (int i = t; i < 32 * 240; i += 256) {
            int el = i / 240, k = i - el * 240;
            int e = e0 + el;
            xs[i] = (k < 128) ? g_agg[(size_t)e * 128 + k]
                              : ef[(size_t)e * 112 + (k - 128)];
        }
        __syncthreads();

        unsigned long long acc2[16];
#pragma unroll
        for (int e = 0; e < 16; e++) acc2[e] = 0ULL;

#pragma unroll 4
        for (int k4 = 0; k4 < 60; k4++) {
            float w0 = W1s[(4 * k4 + 0) * 128 + c];
            float w1 = W1s[(4 * k4 + 1) * 128 + c];
            float w2 = W1s[(4 * k4 + 2) * 128 + c];
            float w3 = W1s[(4 * k4 + 3) * 128 + c];
            unsigned long long wp01 = pack2(w0, w1);
            unsigned long long wp23 = pack2(w2, w3);
#pragma unroll
            for (int e = 0; e < 16; e++) {
                unsigned long long x01, x23;
                lds_v2u64(xs_sa + (unsigned)(e * 240 + 4 * k4) * 4, x01, x23);
                acc2[e] = fma2(x01, wp01, acc2[e]);
                acc2[e] = fma2(x23, wp23, acc2[e]);
            }
        }
#pragma unroll
        for (int e = 0; e < 16; e++) {
            float lo, hi;
            unpack2(acc2[e], lo, hi);
            float v = lo + hi + bias;
            float h = v * __fdividef(1.f, 1.f + __expf(-v));   // silu
            g_hid[(size_t)(e0 + g * 16 + e) * 128 + c] = h;
        }
    }
}

// ---------------------------------------------------------------------------
// Kernel D2: out = hid @ W2 + b2, f32x2 packed
// ---------------------------------------------------------------------------
__global__ __launch_bounds__(288) void kD2(const float* __restrict__ W2,
                                           const float* __restrict__ b2,
                                           float* __restrict__ out) {
    extern __shared__ float smD2[];
    float* W2s = smD2;                 // [128][144]
    float* xs  = smD2 + 128 * 144;     // [32][128]
    int t = threadIdx.x;

    for (int i = t; i < 128 * 144; i += 288) W2s[i] = W2[i];
    __syncthreads();

    int c = t % 144, g = t / 144;
    float bias = b2[c];
    unsigned xs_sa = (unsigned)__cvta_generic_to_shared(xs + (size_t)g * 16 * 128);
    const int ntiles = NEg / 32;
    for (int tile = blockIdx.x; tile < ntiles; tile += gridDim.x) {
        int e0 = tile * 32;
        __syncthreads();
        for (int i = t; i < 32 * 128; i += 288)
            xs[i] = g_hid[(size_t)e0 * 128 + i];
        __syncthreads();

        unsigned long long acc2[16];
#pragma unroll
        for (int e = 0; e < 16; e++) acc2[e] = 0ULL;

#pragma unroll 4
        for (int k4 = 0; k4 < 32; k4++) {
            float w0 = W2s[(4 * k4 + 0) * 144 + c];
            float w1 = W2s[(4 * k4 + 1) * 144 + c];
            float w2 = W2s[(4 * k4 + 2) * 144 + c];
            float w3 = W2s[(4 * k4 + 3) * 144 + c];
            unsigned long long wp01 = pack2(w0, w1);
            unsigned long long wp23 = pack2(w2, w3);
#pragma unroll
            for (int e = 0; e < 16; e++) {
                unsigned long long x01, x23;
                lds_v2u64(xs_sa + (unsigned)(e * 128 + 4 * k4) * 4, x01, x23);
                acc2[e] = fma2(x01, wp01, acc2[e]);
                acc2[e] = fma2(x23, wp23, acc2[e]);
            }
        }
#pragma unroll
        for (int e = 0; e < 16; e++) {
            float lo, hi;
            unpack2(acc2[e], lo, hi);
            out[(size_t)(e0 + g * 16 + e) * 144 + c] = lo + hi + bias;
        }
    }
}

// ---------------------------------------------------------------------------
extern "C" void kernel_launch(void* const* d_in, const int* in_sizes, int n_in,
                              void* d_out, int out_size) {
    const float* atom_fea = (const float*)d_in[0];
    const float* edge_fea = (const float*)d_in[1];
    const int*   sai      = (const int*)  d_in[2];
    const int*   sei      = (const int*)  d_in[3];
    const float* ang      = (const float*)d_in[4];
    const int*   sidx     = (const int*)  d_in[5];
    const float* dist     = (const float*)d_in[6];
    const float* Wf       = (const float*)d_in[7];
    const float* bf       = (const float*)d_in[8];
    const float* Ws       = (const float*)d_in[9];
    const float* bs       = (const float*)d_in[10];
    const float* W1       = (const float*)d_in[11];
    const float* b1       = (const float*)d_in[12];
    const float* W2       = (const float*)d_in[13];
    const float* b2       = (const float*)d_in[14];
    float* out = (float*)d_out;

    static bool attr_done = false;
    if (!attr_done) {
        cudaFuncSetAttribute(kB,  cudaFuncAttributeMaxDynamicSharedMemorySize, 112*128*4 + 32*112*4);
        cudaFuncSetAttribute(kD1, cudaFuncAttributeMaxDynamicSharedMemorySize, 240*128*4 + 32*240*4);
        cudaFuncSetAttribute(kD2, cudaFuncAttributeMaxDynamicSharedMemorySize, 128*144*4 + 32*128*4);
        attr_done = true;
    }

    // zero scatter buffer
    {
        size_t n4 = (size_t)2 * NEg * 64 / 4;
        int blocks = (int)((n4 + 255) / 256);
        kZero<<<blocks, 256>>>();
    }
    kA<<<(NA + 31) / 32, 256>>>(atom_fea, Wf, Ws);
    kB<<<444, 256, 112*128*4 + 32*112*4>>>(edge_fea, Wf, Ws);
    kC<<<2048, 256>>>(sai, sei, ang, sidx, dist, Wf, bf, Ws, bs);
    kD1<<<148, 256, 240*128*4 + 32*240*4>>>(edge_fea, W1, b1);
    kD2<<<296, 288, 128*144*4 + 32*128*4>>>(W2, b2, out);
}

// round 4
// speedup vs baseline: 1.2984x; 1.2984x over previous
#include <cuda_runtime.h>
#include <math.h>

#define NA   50000
#define NEg  200000
#define NSg  1000000
#define HIDF 128
#define OUTF 144

// Scratch (static device globals; no allocation allowed)
__device__ float g_PA[(size_t)NA * 256];        // per-atom: [f0|f1|s0|s1] each 64
__device__ float g_PE[(size_t)NEg * 128];       // per-edge: [f_e|s_e] each 64
__device__ float g_agg[(size_t)2 * NEg * 64];   // scatter target
__device__ float g_hid[(size_t)NEg * HIDF];     // stage-5 hidden

// ---------------------------------------------------------------------------
// f32x2 packed-math helpers (Blackwell FFMA2 path)
// ---------------------------------------------------------------------------
__device__ __forceinline__ unsigned long long pack2(float lo, float hi) {
    unsigned long long r;
    asm("mov.b64 %0, {%1, %2};" : "=l"(r) : "f"(lo), "f"(hi));
    return r;
}
__device__ __forceinline__ void unpack2(unsigned long long v, float& lo, float& hi) {
    asm("mov.b64 {%0, %1}, %2;" : "=f"(lo), "=f"(hi) : "l"(v));
}
__device__ __forceinline__ unsigned long long fma2(unsigned long long a,
                                                   unsigned long long b,
                                                   unsigned long long c) {
    unsigned long long d;
    asm("fma.rn.f32x2 %0, %1, %2, %3;" : "=l"(d) : "l"(a), "l"(b), "l"(c));
    return d;
}
// 16B shared load as two packed f32x2 (no pack instructions needed)
__device__ __forceinline__ void lds_v2u64(unsigned sa, unsigned long long& x0,
                                          unsigned long long& x1) {
    asm("ld.shared.v2.u64 {%0, %1}, [%2];" : "=l"(x0), "=l"(x1) : "r"(sa));
}

// ---------------------------------------------------------------------------
// Zero the scatter buffer
// ---------------------------------------------------------------------------
__global__ void kZero() {
    size_t i = (size_t)blockIdx.x * blockDim.x + threadIdx.x;
    size_t n4 = (size_t)2 * NEg * 64 / 4;
    if (i < n4) reinterpret_cast<float4*>(g_agg)[i] = make_float4(0.f, 0.f, 0.f, 0.f);
}

// ---------------------------------------------------------------------------
// Kernel A: per-atom projections
// ---------------------------------------------------------------------------
__global__ __launch_bounds__(256) void kA(const float* __restrict__ atom,
                                          const float* __restrict__ Wf,
                                          const float* __restrict__ Ws) {
    int t = threadIdx.x;
    int m = t >> 6;
    int c = t & 63;
    const float* W = ((m < 2) ? Wf : Ws) + (size_t)(m & 1) * 64 * 64;
    float w[64];
#pragma unroll
    for (int k = 0; k < 64; k++) w[k] = W[k * 64 + c];

    __shared__ float xs[32][64];
    int a0 = blockIdx.x * 32;
    for (int i = t; i < 32 * 64; i += 256) {
        int a = a0 + (i >> 6);
        xs[i >> 6][i & 63] = (a < NA) ? atom[(size_t)a * 64 + (i & 63)] : 0.f;
    }
    __syncthreads();

    for (int j = 0; j < 32; j++) {
        int a = a0 + j;
        if (a >= NA) break;
        const float4* x4 = reinterpret_cast<const float4*>(xs[j]);
        float acc = 0.f;
#pragma unroll
        for (int k4 = 0; k4 < 16; k4++) {
            float4 v = x4[k4];
            acc = fmaf(v.x, w[4 * k4 + 0], acc);
            acc = fmaf(v.y, w[4 * k4 + 1], acc);
            acc = fmaf(v.z, w[4 * k4 + 2], acc);
            acc = fmaf(v.w, w[4 * k4 + 3], acc);
        }
        g_PA[(size_t)a * 256 + t] = acc;
    }
}

// ---------------------------------------------------------------------------
// Kernel B: per-edge projections, f32x2 packed accumulation
// ---------------------------------------------------------------------------
__global__ __launch_bounds__(256) void kB(const float* __restrict__ ef,
                                          const float* __restrict__ Wf,
                                          const float* __restrict__ Ws) {
    extern __shared__ float smB[];
    float* Wc = smB;                 // [112][128]
    float* xs = smB + 112 * 128;     // [32][112]
    int t = threadIdx.x;

    for (int i = t; i < 112 * 128; i += 256) {
        int k = i >> 7, c = i & 127;
        Wc[i] = (c < 64) ? Wf[(size_t)(128 + k) * 64 + c]
                         : Ws[(size_t)(128 + k) * 64 + (c - 64)];
    }
    __syncthreads();

    int c = t & 127, g = t >> 7;
    unsigned xs_sa = (unsigned)__cvta_generic_to_shared(xs + (size_t)g * 16 * 112);
    const int ntiles = NEg / 32;   // 6250
    for (int tile = blockIdx.x; tile < ntiles; tile += gridDim.x) {
        int e0 = tile * 32;
        __syncthreads();
        for (int i = t; i < 32 * 112; i += 256) {
            int el = i / 112, k = i - el * 112;
            xs[i] = ef[(size_t)(e0 + el) * 112 + k];
        }
        __syncthreads();

        unsigned long long acc2[16];
#pragma unroll
        for (int e = 0; e < 16; e++) acc2[e] = 0ULL;

#pragma unroll 4
        for (int k4 = 0; k4 < 28; k4++) {
            float w0 = Wc[(4 * k4 + 0) * 128 + c];
            float w1 = Wc[(4 * k4 + 1) * 128 + c];
            float w2 = Wc[(4 * k4 + 2) * 128 + c];
            float w3 = Wc[(4 * k4 + 3) * 128 + c];
            unsigned long long wp01 = pack2(w0, w1);
            unsigned long long wp23 = pack2(w2, w3);
#pragma unroll
            for (int e = 0; e < 16; e++) {
                unsigned long long x01, x23;
                lds_v2u64(xs_sa + (unsigned)(e * 112 + 4 * k4) * 4, x01, x23);
                acc2[e] = fma2(x01, wp01, acc2[e]);
                acc2[e] = fma2(x23, wp23, acc2[e]);
            }
        }
#pragma unroll
        for (int e = 0; e < 16; e++) {
            float lo, hi;
            unpack2(acc2[e], lo, hi);
            g_PE[(size_t)(e0 + g * 16 + e) * 128 + c] = lo + hi;
        }
    }
}

// ---------------------------------------------------------------------------
// Kernel C v4: one warp per TWO rows; lane covers column pair (2l,2l+1).
// Weights interleaved in smem as float4 (wf.x,wf.y,ws.x,ws.y): one LDS.128
// per k feeds BOTH rows -> 4KB crossbar per row (half of v2).
// 8 independent FMA chains + 12 outstanding gathers per iteration.
// ---------------------------------------------------------------------------
__global__ __launch_bounds__(256) void kC(const int*   __restrict__ sai,
                                          const int*   __restrict__ sei,
                                          const float* __restrict__ ang,
                                          const int*   __restrict__ sidx,
                                          const float* __restrict__ dist,
                                          const float* __restrict__ Wf,
                                          const float* __restrict__ bf,
                                          const float* __restrict__ Ws,
                                          const float* __restrict__ bs) {
    __shared__ float4 sw[16][32];   // (wf.x, wf.y, ws.x, ws.y) for lane's col pair
    int t = threadIdx.x;
    for (int i = t; i < 512; i += 256) {
        int k = i >> 5, l = i & 31;
        float2 wf2 = reinterpret_cast<const float2*>(Wf + (size_t)(240 + k) * 64)[l];
        float2 ws2 = reinterpret_cast<const float2*>(Ws + (size_t)(240 + k) * 64)[l];
        sw[k][l] = make_float4(wf2.x, wf2.y, ws2.x, ws2.y);
    }
    __syncthreads();

    int lane = t & 31;
    float2 bfv = reinterpret_cast<const float2*>(bf)[lane];
    float2 bsv = reinterpret_cast<const float2*>(bs)[lane];

    unsigned wid = ((unsigned)blockIdx.x * blockDim.x + t) >> 5;
    unsigned nwarps = ((unsigned)gridDim.x * blockDim.x) >> 5;
    const unsigned npairs = NSg / 2;   // 500000

    for (unsigned p = wid; p < npairs; p += nwarps) {
        unsigned s0 = 2 * p, s1 = 2 * p + 1;
        int i00 = sai[2 * s0], i01 = sai[2 * s0 + 1];
        int i10 = sai[2 * s1], i11 = sai[2 * s1 + 1];
        int e0 = sei[s0], e1 = sei[s1];
        int q0 = sidx[s0], q1 = sidx[s1];
        float d0 = dist[e0], d1 = dist[e1];

        const float2* pa00 = reinterpret_cast<const float2*>(g_PA + (size_t)i00 * 256);
        const float2* pa01 = reinterpret_cast<const float2*>(g_PA + (size_t)i01 * 256);
        const float2* pe0  = reinterpret_cast<const float2*>(g_PE + (size_t)e0  * 128);
        const float2* pa10 = reinterpret_cast<const float2*>(g_PA + (size_t)i10 * 256);
        const float2* pa11 = reinterpret_cast<const float2*>(g_PA + (size_t)i11 * 256);
        const float2* pe1  = reinterpret_cast<const float2*>(g_PE + (size_t)e1  * 128);

        // 12 independent gathers (MLP)
        float2 A0 = pa00[lane],      B0 = pa01[32 + lane], C0 = pe0[lane];
        float2 D0 = pa00[64 + lane], E0 = pa01[96 + lane], F0 = pe0[32 + lane];
        float2 A1 = pa10[lane],      B1 = pa11[32 + lane], C1 = pe1[lane];
        float2 D1 = pa10[64 + lane], E1 = pa11[96 + lane], F1 = pe1[32 + lane];

        float vf0x = A0.x + B0.x + C0.x + bfv.x;
        float vf0y = A0.y + B0.y + C0.y + bfv.y;
        float vs0x = D0.x + E0.x + F0.x + bsv.x;
        float vs0y = D0.y + E0.y + F0.y + bsv.y;
        float vf1x = A1.x + B1.x + C1.x + bfv.x;
        float vf1y = A1.y + B1.y + C1.y + bfv.y;
        float vs1x = D1.x + E1.x + F1.x + bsv.x;
        float vs1y = D1.y + E1.y + F1.y + bsv.y;

        const float4* ap0 = reinterpret_cast<const float4*>(ang + (size_t)s0 * 16);
        const float4* ap1 = reinterpret_cast<const float4*>(ang + (size_t)s1 * 16);

#pragma unroll
        for (int k4 = 0; k4 < 4; k4++) {
            float4 a0 = ap0[k4];
            float4 a1 = ap1[k4];
            float aa0[4] = {a0.x, a0.y, a0.z, a0.w};
            float aa1[4] = {a1.x, a1.y, a1.z, a1.w};
#pragma unroll
            for (int j = 0; j < 4; j++) {
                float4 w = sw[4 * k4 + j][lane];
                float u0 = aa0[j], u1 = aa1[j];
                vf0x = fmaf(u0, w.x, vf0x);
                vf0y = fmaf(u0, w.y, vf0y);
                vs0x = fmaf(u0, w.z, vs0x);
                vs0y = fmaf(u0, w.w, vs0y);
                vf1x = fmaf(u1, w.x, vf1x);
                vf1y = fmaf(u1, w.y, vf1y);
                vs1x = fmaf(u1, w.z, vs1x);
                vs1y = fmaf(u1, w.w, vs1y);
            }
        }

        float dec0 = __expf(-d0 * d0 * (1.0f / 18.0f));
        float dec1 = __expf(-d1 * d1 * (1.0f / 18.0f));

        float o0x = __fdividef(dec0, 1.f + __expf(-vf0x)) *
                    (fmaxf(vs0x, 0.f) + __logf(1.f + __expf(-fabsf(vs0x))));
        float o0y = __fdividef(dec0, 1.f + __expf(-vf0y)) *
                    (fmaxf(vs0y, 0.f) + __logf(1.f + __expf(-fabsf(vs0y))));
        float o1x = __fdividef(dec1, 1.f + __expf(-vf1x)) *
                    (fmaxf(vs1x, 0.f) + __logf(1.f + __expf(-fabsf(vs1x))));
        float o1y = __fdividef(dec1, 1.f + __expf(-vf1y)) *
                    (fmaxf(vs1y, 0.f) + __logf(1.f + __expf(-fabsf(vs1y))));

        float* dst0 = g_agg + (size_t)q0 * 64 + 2 * lane;
        float* dst1 = g_agg + (size_t)q1 * 64 + 2 * lane;
        atomicAdd(dst0,     o0x);
        atomicAdd(dst0 + 1, o0y);
        atomicAdd(dst1,     o1x);
        atomicAdd(dst1 + 1, o1y);
    }
}

// ---------------------------------------------------------------------------
// Kernel D1: hid = silu([agg0|agg1|ef] @ W1 + b1), f32x2 packed
// ---------------------------------------------------------------------------
__global__ __launch_bounds__(256) void kD1(const float* __restrict__ ef,
                                           const float* __restrict__ W1,
                                           const float* __restrict__ b1) {
    extern __shared__ float smD1[];
    float* W1s = smD1;                 // [240][128]
    float* xs  = smD1 + 240 * 128;     // [32][240]
    int t = threadIdx.x;

    for (int i = t; i < 240 * 128; i += 256) W1s[i] = W1[i];
    __syncthreads();

    int c = t & 127, g = t >> 7;
    float bias = b1[c];
    unsigned xs_sa = (unsigned)__cvta_generic_to_shared(xs + (size_t)g * 16 * 240);
    const int ntiles = NEg / 32;
    for (int tile = blockIdx.x; tile < ntiles; tile += gridDim.x) {
        int e0 = tile * 32;
        __syncthreads();
        for (int i = t; i < 32 * 240; i += 256) {
            int el = i / 240, k = i - el * 240;
            int e = e0 + el;
            xs[i] = (k < 128) ? g_agg[(size_t)e * 128 + k]
                              : ef[(size_t)e * 112 + (k - 128)];
        }
        __syncthreads();

        unsigned long long acc2[16];
#pragma unroll
        for (int e = 0; e < 16; e++) acc2[e] = 0ULL;

#pragma unroll 4
        for (int k4 = 0; k4 < 60; k4++) {
            float w0 = W1s[(4 * k4 + 0) * 128 + c];
            float w1 = W1s[(4 * k4 + 1) * 128 + c];
            float w2 = W1s[(4 * k4 + 2) * 128 + c];
            float w3 = W1s[(4 * k4 + 3) * 128 + c];
            unsigned long long wp01 = pack2(w0, w1);
            unsigned long long wp23 = pack2(w2, w3);
#pragma unroll
            for (int e = 0; e < 16; e++) {
                unsigned long long x01, x23;
                lds_v2u64(xs_sa + (unsigned)(e * 240 + 4 * k4) * 4, x01, x23);
                acc2[e] = fma2(x01, wp01, acc2[e]);
                acc2[e] = fma2(x23, wp23, acc2[e]);
            }
        }
#pragma unroll
        for (int e = 0; e < 16; e++) {
            float lo, hi;
            unpack2(acc2[e], lo, hi);
            float v = lo + hi + bias;
            float h = v * __fdividef(1.f, 1.f + __expf(-v));   // silu
            g_hid[(size_t)(e0 + g * 16 + e) * 128 + c] = h;
        }
    }
}

// ---------------------------------------------------------------------------
// Kernel D2: out = hid @ W2 + b2, f32x2 packed
// ---------------------------------------------------------------------------
__global__ __launch_bounds__(288) void kD2(const float* __restrict__ W2,
                                           const float* __restrict__ b2,
                                           float* __restrict__ out) {
    extern __shared__ float smD2[];
    float* W2s = smD2;                 // [128][144]
    float* xs  = smD2 + 128 * 144;     // [32][128]
    int t = threadIdx.x;

    for (int i = t; i < 128 * 144; i += 288) W2s[i] = W2[i];
    __syncthreads();

    int c = t % 144, g = t / 144;
    float bias = b2[c];
    unsigned xs_sa = (unsigned)__cvta_generic_to_shared(xs + (size_t)g * 16 * 128);
    const int ntiles = NEg / 32;
    for (int tile = blockIdx.x; tile < ntiles; tile += gridDim.x) {
        int e0 = tile * 32;
        __syncthreads();
        for (int i = t; i < 32 * 128; i += 288)
            xs[i] = g_hid[(size_t)e0 * 128 + i];
        __syncthreads();

        unsigned long long acc2[16];
#pragma unroll
        for (int e = 0; e < 16; e++) acc2[e] = 0ULL;

#pragma unroll 4
        for (int k4 = 0; k4 < 32; k4++) {
            float w0 = W2s[(4 * k4 + 0) * 144 + c];
            float w1 = W2s[(4 * k4 + 1) * 144 + c];
            float w2 = W2s[(4 * k4 + 2) * 144 + c];
            float w3 = W2s[(4 * k4 + 3) * 144 + c];
            unsigned long long wp01 = pack2(w0, w1);
            unsigned long long wp23 = pack2(w2, w3);
#pragma unroll
            for (int e = 0; e < 16; e++) {
                unsigned long long x01, x23;
                lds_v2u64(xs_sa + (unsigned)(e * 128 + 4 * k4) * 4, x01, x23);
                acc2[e] = fma2(x01, wp01, acc2[e]);
                acc2[e] = fma2(x23, wp23, acc2[e]);
            }
        }
#pragma unroll
        for (int e = 0; e < 16; e++) {
            float lo, hi;
            unpack2(acc2[e], lo, hi);
            out[(size_t)(e0 + g * 16 + e) * 144 + c] = lo + hi + bias;
        }
    }
}

// ---------------------------------------------------------------------------
extern "C" void kernel_launch(void* const* d_in, const int* in_sizes, int n_in,
                              void* d_out, int out_size) {
    const float* atom_fea = (const float*)d_in[0];
    const float* edge_fea = (const float*)d_in[1];
    const int*   sai      = (const int*)  d_in[2];
    const int*   sei      = (const int*)  d_in[3];
    const float* ang      = (const float*)d_in[4];
    const int*   sidx     = (const int*)  d_in[5];
    const float* dist     = (const float*)d_in[6];
    const float* Wf       = (const float*)d_in[7];
    const float* bf       = (const float*)d_in[8];
    const float* Ws       = (const float*)d_in[9];
    const float* bs       = (const float*)d_in[10];
    const float* W1       = (const float*)d_in[11];
    const float* b1       = (const float*)d_in[12];
    const float* W2       = (const float*)d_in[13];
    const float* b2       = (const float*)d_in[14];
    float* out = (float*)d_out;

    static bool attr_done = false;
    if (!attr_done) {
        cudaFuncSetAttribute(kB,  cudaFuncAttributeMaxDynamicSharedMemorySize, 112*128*4 + 32*112*4);
        cudaFuncSetAttribute(kD1, cudaFuncAttributeMaxDynamicSharedMemorySize, 240*128*4 + 32*240*4);
        cudaFuncSetAttribute(kD2, cudaFuncAttributeMaxDynamicSharedMemorySize, 128*144*4 + 32*128*4);
        attr_done = true;
    }

    // zero scatter buffer
    {
        size_t n4 = (size_t)2 * NEg * 64 / 4;
        int blocks = (int)((n4 + 255) / 256);
        kZero<<<blocks, 256>>>();
    }
    kA<<<(NA + 31) / 32, 256>>>(atom_fea, Wf, Ws);
    kB<<<444, 256, 112*128*4 + 32*112*4>>>(edge_fea, Wf, Ws);
    kC<<<2048, 256>>>(sai, sei, ang, sidx, dist, Wf, bf, Ws, bs);
    kD1<<<148, 256, 240*128*4 + 32*240*4>>>(edge_fea, W1, b1);
    kD2<<<296, 288, 128*144*4 + 32*128*4>>>(W2, b2, out);
}

// round 5
// speedup vs baseline: 1.5603x; 1.2017x over previous
#include <cuda_runtime.h>
#include <math.h>

#define NA   50000
#define NEg  200000
#define NSg  1000000
#define HIDF 128
#define OUTF 144
#define XSTR 68   // padded k-major x tile stride (floats), 16B-aligned, conflict-light

// Scratch (static device globals; no allocation allowed)
__device__ float g_PA[(size_t)NA * 256];        // per-atom: [f0|f1|s0|s1] each 64
__device__ float g_PE[(size_t)NEg * 128];       // per-edge: [f_e|s_e] each 64
__device__ float g_agg[(size_t)2 * NEg * 64];   // scatter target
__device__ float g_hid[(size_t)NEg * HIDF];     // stage-5 hidden

// ---------------------------------------------------------------------------
// f32x2 packed-math helpers
// ---------------------------------------------------------------------------
__device__ __forceinline__ unsigned long long pack2(float lo, float hi) {
    unsigned long long r;
    asm("mov.b64 %0, {%1, %2};" : "=l"(r) : "f"(lo), "f"(hi));
    return r;
}
__device__ __forceinline__ void unpack2(unsigned long long v, float& lo, float& hi) {
    asm("mov.b64 {%0, %1}, %2;" : "=f"(lo), "=f"(hi) : "l"(v));
}
__device__ __forceinline__ unsigned long long fma2(unsigned long long a,
                                                   unsigned long long b,
                                                   unsigned long long c) {
    unsigned long long d;
    asm("fma.rn.f32x2 %0, %1, %2, %3;" : "=l"(d) : "l"(a), "l"(b), "l"(c));
    return d;
}
__device__ __forceinline__ void lds_v2u64(unsigned sa, unsigned long long& x0,
                                          unsigned long long& x1) {
    asm("ld.shared.v2.u64 {%0, %1}, [%2];" : "=l"(x0), "=l"(x1) : "r"(sa));
}

// ---------------------------------------------------------------------------
__global__ void kZero() {
    size_t i = (size_t)blockIdx.x * blockDim.x + threadIdx.x;
    size_t n4 = (size_t)2 * NEg * 64 / 4;
    if (i < n4) reinterpret_cast<float4*>(g_agg)[i] = make_float4(0.f, 0.f, 0.f, 0.f);
}

// ---------------------------------------------------------------------------
// Kernel A: per-atom projections (unchanged)
// ---------------------------------------------------------------------------
__global__ __launch_bounds__(256) void kA(const float* __restrict__ atom,
                                          const float* __restrict__ Wf,
                                          const float* __restrict__ Ws) {
    int t = threadIdx.x;
    int m = t >> 6;
    int c = t & 63;
    const float* W = ((m < 2) ? Wf : Ws) + (size_t)(m & 1) * 64 * 64;
    float w[64];
#pragma unroll
    for (int k = 0; k < 64; k++) w[k] = W[k * 64 + c];

    __shared__ float xs[32][64];
    int a0 = blockIdx.x * 32;
    for (int i = t; i < 32 * 64; i += 256) {
        int a = a0 + (i >> 6);
        xs[i >> 6][i & 63] = (a < NA) ? atom[(size_t)a * 64 + (i & 63)] : 0.f;
    }
    __syncthreads();

    for (int j = 0; j < 32; j++) {
        int a = a0 + j;
        if (a >= NA) break;
        const float4* x4 = reinterpret_cast<const float4*>(xs[j]);
        float acc = 0.f;
#pragma unroll
        for (int k4 = 0; k4 < 16; k4++) {
            float4 v = x4[k4];
            acc = fmaf(v.x, w[4 * k4 + 0], acc);
            acc = fmaf(v.y, w[4 * k4 + 1], acc);
            acc = fmaf(v.z, w[4 * k4 + 2], acc);
            acc = fmaf(v.w, w[4 * k4 + 3], acc);
        }
        g_PA[(size_t)a * 256 + t] = acc;
    }
}

// ---------------------------------------------------------------------------
// Shared inner engine: 8-edge x 4-col register outer product, f32x2 packed.
// xs is k-major [K][XSTR]; W k-major [K][NC]. Returns 16 packed accs.
// ---------------------------------------------------------------------------
// (inlined manually per kernel to keep K compile-time)

// ---------------------------------------------------------------------------
// Kernel B: PE[e][c] = sum_k ef[e][k] * Wc[k][c], K=112, NC=128
// 256 threads: cg = t&31 (4 cols), eg = t>>5 (8 edges). Tile = 64 edges.
// ---------------------------------------------------------------------------
__global__ __launch_bounds__(256) void kB(const float* __restrict__ ef,
                                          const float* __restrict__ Wf,
                                          const float* __restrict__ Ws) {
    extern __shared__ float smB[];
    float* Wc = smB;                 // [112][128]
    float* xs = smB + 112 * 128;     // [112][XSTR]
    int t = threadIdx.x;

    for (int i = t; i < 112 * 128; i += 256) {
        int k = i >> 7, c = i & 127;
        Wc[i] = (c < 64) ? Wf[(size_t)(128 + k) * 64 + c]
                         : Ws[(size_t)(128 + k) * 64 + (c - 64)];
    }

    int cg = t & 31, eg = t >> 5;
    int c0 = cg * 4, e0 = eg * 8;
    unsigned xs_sa = (unsigned)__cvta_generic_to_shared(xs);
    const int ntiles = NEg / 64;   // 3125
    for (int tile = blockIdx.x; tile < ntiles; tile += gridDim.x) {
        int eb = tile * 64;
        __syncthreads();
        // transpose-stage x: 64 edges x 28 k-quads
        for (int i = t; i < 64 * 28; i += 256) {
            int e = i / 28, kq = i - e * 28;
            float4 v = reinterpret_cast<const float4*>(ef + (size_t)(eb + e) * 112)[kq];
            xs[(4 * kq + 0) * XSTR + e] = v.x;
            xs[(4 * kq + 1) * XSTR + e] = v.y;
            xs[(4 * kq + 2) * XSTR + e] = v.z;
            xs[(4 * kq + 3) * XSTR + e] = v.w;
        }
        __syncthreads();

        unsigned long long acc[16];
#pragma unroll
        for (int i = 0; i < 16; i++) acc[i] = 0ULL;

#pragma unroll 4
        for (int k = 0; k < 112; k++) {
            float4 wv = *reinterpret_cast<const float4*>(Wc + k * 128 + c0);
            unsigned long long x01, x23, x45, x67;
            unsigned base = xs_sa + (unsigned)(k * XSTR + e0) * 4;
            lds_v2u64(base, x01, x23);
            lds_v2u64(base + 16, x45, x67);
            unsigned long long w0 = pack2(wv.x, wv.x);
            unsigned long long w1 = pack2(wv.y, wv.y);
            unsigned long long w2 = pack2(wv.z, wv.z);
            unsigned long long w3 = pack2(wv.w, wv.w);
            acc[0]  = fma2(x01, w0, acc[0]);  acc[1]  = fma2(x23, w0, acc[1]);
            acc[2]  = fma2(x45, w0, acc[2]);  acc[3]  = fma2(x67, w0, acc[3]);
            acc[4]  = fma2(x01, w1, acc[4]);  acc[5]  = fma2(x23, w1, acc[5]);
            acc[6]  = fma2(x45, w1, acc[6]);  acc[7]  = fma2(x67, w1, acc[7]);
            acc[8]  = fma2(x01, w2, acc[8]);  acc[9]  = fma2(x23, w2, acc[9]);
            acc[10] = fma2(x45, w2, acc[10]); acc[11] = fma2(x67, w2, acc[11]);
            acc[12] = fma2(x01, w3, acc[12]); acc[13] = fma2(x23, w3, acc[13]);
            acc[14] = fma2(x45, w3, acc[14]); acc[15] = fma2(x67, w3, acc[15]);
        }

        // epilogue: acc[c*4+ep] holds (edge e0+2ep, e0+2ep+1) for col c0+c
#pragma unroll
        for (int ep = 0; ep < 4; ep++) {
            float lo0, hi0, lo1, hi1, lo2, hi2, lo3, hi3;
            unpack2(acc[0 + ep],  lo0, hi0);
            unpack2(acc[4 + ep],  lo1, hi1);
            unpack2(acc[8 + ep],  lo2, hi2);
            unpack2(acc[12 + ep], lo3, hi3);
            float4 olo = make_float4(lo0, lo1, lo2, lo3);
            float4 ohi = make_float4(hi0, hi1, hi2, hi3);
            int elo = eb + e0 + 2 * ep, ehi = elo + 1;
            *reinterpret_cast<float4*>(g_PE + (size_t)elo * 128 + c0) = olo;
            *reinterpret_cast<float4*>(g_PE + (size_t)ehi * 128 + c0) = ohi;
        }
    }
}

// ---------------------------------------------------------------------------
// Kernel C v4 (unchanged from R4): one warp per two rows
// ---------------------------------------------------------------------------
__global__ __launch_bounds__(256) void kC(const int*   __restrict__ sai,
                                          const int*   __restrict__ sei,
                                          const float* __restrict__ ang,
                                          const int*   __restrict__ sidx,
                                          const float* __restrict__ dist,
                                          const float* __restrict__ Wf,
                                          const float* __restrict__ bf,
                                          const float* __restrict__ Ws,
                                          const float* __restrict__ bs) {
    __shared__ float4 sw[16][32];
    int t = threadIdx.x;
    for (int i = t; i < 512; i += 256) {
        int k = i >> 5, l = i & 31;
        float2 wf2 = reinterpret_cast<const float2*>(Wf + (size_t)(240 + k) * 64)[l];
        float2 ws2 = reinterpret_cast<const float2*>(Ws + (size_t)(240 + k) * 64)[l];
        sw[k][l] = make_float4(wf2.x, wf2.y, ws2.x, ws2.y);
    }
    __syncthreads();

    int lane = t & 31;
    float2 bfv = reinterpret_cast<const float2*>(bf)[lane];
    float2 bsv = reinterpret_cast<const float2*>(bs)[lane];

    unsigned wid = ((unsigned)blockIdx.x * blockDim.x + t) >> 5;
    unsigned nwarps = ((unsigned)gridDim.x * blockDim.x) >> 5;
    const unsigned npairs = NSg / 2;

    for (unsigned p = wid; p < npairs; p += nwarps) {
        unsigned s0 = 2 * p, s1 = 2 * p + 1;
        int i00 = sai[2 * s0], i01 = sai[2 * s0 + 1];
        int i10 = sai[2 * s1], i11 = sai[2 * s1 + 1];
        int e0 = sei[s0], e1 = sei[s1];
        int q0 = sidx[s0], q1 = sidx[s1];
        float d0 = dist[e0], d1 = dist[e1];

        const float2* pa00 = reinterpret_cast<const float2*>(g_PA + (size_t)i00 * 256);
        const float2* pa01 = reinterpret_cast<const float2*>(g_PA + (size_t)i01 * 256);
        const float2* pe0  = reinterpret_cast<const float2*>(g_PE + (size_t)e0  * 128);
        const float2* pa10 = reinterpret_cast<const float2*>(g_PA + (size_t)i10 * 256);
        const float2* pa11 = reinterpret_cast<const float2*>(g_PA + (size_t)i11 * 256);
        const float2* pe1  = reinterpret_cast<const float2*>(g_PE + (size_t)e1  * 128);

        float2 A0 = pa00[lane],      B0 = pa01[32 + lane], C0 = pe0[lane];
        float2 D0 = pa00[64 + lane], E0 = pa01[96 + lane], F0 = pe0[32 + lane];
        float2 A1 = pa10[lane],      B1 = pa11[32 + lane], C1 = pe1[lane];
        float2 D1 = pa10[64 + lane], E1 = pa11[96 + lane], F1 = pe1[32 + lane];

        float vf0x = A0.x + B0.x + C0.x + bfv.x;
        float vf0y = A0.y + B0.y + C0.y + bfv.y;
        float vs0x = D0.x + E0.x + F0.x + bsv.x;
        float vs0y = D0.y + E0.y + F0.y + bsv.y;
        float vf1x = A1.x + B1.x + C1.x + bfv.x;
        float vf1y = A1.y + B1.y + C1.y + bfv.y;
        float vs1x = D1.x + E1.x + F1.x + bsv.x;
        float vs1y = D1.y + E1.y + F1.y + bsv.y;

        const float4* ap0 = reinterpret_cast<const float4*>(ang + (size_t)s0 * 16);
        const float4* ap1 = reinterpret_cast<const float4*>(ang + (size_t)s1 * 16);

#pragma unroll
        for (int k4 = 0; k4 < 4; k4++) {
            float4 a0 = ap0[k4];
            float4 a1 = ap1[k4];
            float aa0[4] = {a0.x, a0.y, a0.z, a0.w};
            float aa1[4] = {a1.x, a1.y, a1.z, a1.w};
#pragma unroll
            for (int j = 0; j < 4; j++) {
                float4 w = sw[4 * k4 + j][lane];
                float u0 = aa0[j], u1 = aa1[j];
                vf0x = fmaf(u0, w.x, vf0x);
                vf0y = fmaf(u0, w.y, vf0y);
                vs0x = fmaf(u0, w.z, vs0x);
                vs0y = fmaf(u0, w.w, vs0y);
                vf1x = fmaf(u1, w.x, vf1x);
                vf1y = fmaf(u1, w.y, vf1y);
                vs1x = fmaf(u1, w.z, vs1x);
                vs1y = fmaf(u1, w.w, vs1y);
            }
        }

        float dec0 = __expf(-d0 * d0 * (1.0f / 18.0f));
        float dec1 = __expf(-d1 * d1 * (1.0f / 18.0f));

        float o0x = __fdividef(dec0, 1.f + __expf(-vf0x)) *
                    (fmaxf(vs0x, 0.f) + __logf(1.f + __expf(-fabsf(vs0x))));
        float o0y = __fdividef(dec0, 1.f + __expf(-vf0y)) *
                    (fmaxf(vs0y, 0.f) + __logf(1.f + __expf(-fabsf(vs0y))));
        float o1x = __fdividef(dec1, 1.f + __expf(-vf1x)) *
                    (fmaxf(vs1x, 0.f) + __logf(1.f + __expf(-fabsf(vs1x))));
        float o1y = __fdividef(dec1, 1.f + __expf(-vf1y)) *
                    (fmaxf(vs1y, 0.f) + __logf(1.f + __expf(-fabsf(vs1y))));

        float* dst0 = g_agg + (size_t)q0 * 64 + 2 * lane;
        float* dst1 = g_agg + (size_t)q1 * 64 + 2 * lane;
        atomicAdd(dst0,     o0x);
        atomicAdd(dst0 + 1, o0y);
        atomicAdd(dst1,     o1x);
        atomicAdd(dst1 + 1, o1y);
    }
}

// ---------------------------------------------------------------------------
// Kernel D1: hid = silu([agg0|agg1|ef] @ W1 + b1); K=240, NC=128
// 256 threads, 64-edge tile, 8e x 4c per thread
// ---------------------------------------------------------------------------
__global__ __launch_bounds__(256) void kD1(const float* __restrict__ ef,
                                           const float* __restrict__ W1,
                                           const float* __restrict__ b1) {
    extern __shared__ float smD1[];
    float* W1s = smD1;                 // [240][128]
    float* xs  = smD1 + 240 * 128;     // [240][XSTR]
    int t = threadIdx.x;

    for (int i = t; i < 240 * 128; i += 256) W1s[i] = W1[i];

    int cg = t & 31, eg = t >> 5;
    int c0 = cg * 4, e0 = eg * 8;
    float4 bv = *reinterpret_cast<const float4*>(b1 + c0);
    unsigned xs_sa = (unsigned)__cvta_generic_to_shared(xs);
    const int ntiles = NEg / 64;
    for (int tile = blockIdx.x; tile < ntiles; tile += gridDim.x) {
        int eb = tile * 64;
        __syncthreads();
        // transpose-stage x: 64 edges x 60 k-quads (k<128: agg, else ef)
        for (int i = t; i < 64 * 60; i += 256) {
            int e = i / 60, kq = i - e * 60;
            float4 v;
            if (kq < 32)
                v = reinterpret_cast<const float4*>(g_agg + (size_t)(eb + e) * 128)[kq];
            else
                v = reinterpret_cast<const float4*>(ef + (size_t)(eb + e) * 112)[kq - 32];
            xs[(4 * kq + 0) * XSTR + e] = v.x;
            xs[(4 * kq + 1) * XSTR + e] = v.y;
            xs[(4 * kq + 2) * XSTR + e] = v.z;
            xs[(4 * kq + 3) * XSTR + e] = v.w;
        }
        __syncthreads();

        unsigned long long acc[16];
#pragma unroll
        for (int i = 0; i < 16; i++) acc[i] = 0ULL;

#pragma unroll 4
        for (int k = 0; k < 240; k++) {
            float4 wv = *reinterpret_cast<const float4*>(W1s + k * 128 + c0);
            unsigned long long x01, x23, x45, x67;
            unsigned base = xs_sa + (unsigned)(k * XSTR + e0) * 4;
            lds_v2u64(base, x01, x23);
            lds_v2u64(base + 16, x45, x67);
            unsigned long long w0 = pack2(wv.x, wv.x);
            unsigned long long w1 = pack2(wv.y, wv.y);
            unsigned long long w2 = pack2(wv.z, wv.z);
            unsigned long long w3 = pack2(wv.w, wv.w);
            acc[0]  = fma2(x01, w0, acc[0]);  acc[1]  = fma2(x23, w0, acc[1]);
            acc[2]  = fma2(x45, w0, acc[2]);  acc[3]  = fma2(x67, w0, acc[3]);
            acc[4]  = fma2(x01, w1, acc[4]);  acc[5]  = fma2(x23, w1, acc[5]);
            acc[6]  = fma2(x45, w1, acc[6]);  acc[7]  = fma2(x67, w1, acc[7]);
            acc[8]  = fma2(x01, w2, acc[8]);  acc[9]  = fma2(x23, w2, acc[9]);
            acc[10] = fma2(x45, w2, acc[10]); acc[11] = fma2(x67, w2, acc[11]);
            acc[12] = fma2(x01, w3, acc[12]); acc[13] = fma2(x23, w3, acc[13]);
            acc[14] = fma2(x45, w3, acc[14]); acc[15] = fma2(x67, w3, acc[15]);
        }

#pragma unroll
        for (int ep = 0; ep < 4; ep++) {
            float lo0, hi0, lo1, hi1, lo2, hi2, lo3, hi3;
            unpack2(acc[0 + ep],  lo0, hi0);
            unpack2(acc[4 + ep],  lo1, hi1);
            unpack2(acc[8 + ep],  lo2, hi2);
            unpack2(acc[12 + ep], lo3, hi3);
            float v0 = lo0 + bv.x, v1 = lo1 + bv.y, v2 = lo2 + bv.z, v3 = lo3 + bv.w;
            float u0 = hi0 + bv.x, u1 = hi1 + bv.y, u2 = hi2 + bv.z, u3 = hi3 + bv.w;
            float4 olo = make_float4(v0 * __fdividef(1.f, 1.f + __expf(-v0)),
                                     v1 * __fdividef(1.f, 1.f + __expf(-v1)),
                                     v2 * __fdividef(1.f, 1.f + __expf(-v2)),
                                     v3 * __fdividef(1.f, 1.f + __expf(-v3)));
            float4 ohi = make_float4(u0 * __fdividef(1.f, 1.f + __expf(-u0)),
                                     u1 * __fdividef(1.f, 1.f + __expf(-u1)),
                                     u2 * __fdividef(1.f, 1.f + __expf(-u2)),
                                     u3 * __fdividef(1.f, 1.f + __expf(-u3)));
            int elo = eb + e0 + 2 * ep, ehi = elo + 1;
            *reinterpret_cast<float4*>(g_hid + (size_t)elo * 128 + c0) = olo;
            *reinterpret_cast<float4*>(g_hid + (size_t)ehi * 128 + c0) = ohi;
        }
    }
}

// ---------------------------------------------------------------------------
// Kernel D2: out = hid @ W2 + b2; K=128, NC=144
// 288 threads (cg = t%36, eg = t/36), 64-edge tile, 8e x 4c per thread
// ---------------------------------------------------------------------------
__global__ __launch_bounds__(288) void kD2(const float* __restrict__ W2,
                                           const float* __restrict__ b2,
                                           float* __restrict__ out) {
    extern __shared__ float smD2[];
    float* W2s = smD2;                 // [128][144]
    float* xs  = smD2 + 128 * 144;     // [128][XSTR]
    int t = threadIdx.x;

    for (int i = t; i < 128 * 144; i += 288) W2s[i] = W2[i];

    int cg = t % 36, eg = t / 36;
    int c0 = cg * 4, e0 = eg * 8;
    float4 bv = *reinterpret_cast<const float4*>(b2 + c0);
    unsigned xs_sa = (unsigned)__cvta_generic_to_shared(xs);
    const int ntiles = NEg / 64;
    for (int tile = blockIdx.x; tile < ntiles; tile += gridDim.x) {
        int eb = tile * 64;
        __syncthreads();
        for (int i = t; i < 64 * 32; i += 288) {
            int e = i >> 5, kq = i & 31;
            float4 v = reinterpret_cast<const float4*>(g_hid + (size_t)(eb + e) * 128)[kq];
            xs[(4 * kq + 0) * XSTR + e] = v.x;
            xs[(4 * kq + 1) * XSTR + e] = v.y;
            xs[(4 * kq + 2) * XSTR + e] = v.z;
            xs[(4 * kq + 3) * XSTR + e] = v.w;
        }
        __syncthreads();

        unsigned long long acc[16];
#pragma unroll
        for (int i = 0; i < 16; i++) acc[i] = 0ULL;

#pragma unroll 4
        for (int k = 0; k < 128; k++) {
            float4 wv = *reinterpret_cast<const float4*>(W2s + k * 144 + c0);
            unsigned long long x01, x23, x45, x67;
            unsigned base = xs_sa + (unsigned)(k * XSTR + e0) * 4;
            lds_v2u64(base, x01, x23);
            lds_v2u64(base + 16, x45, x67);
            unsigned long long w0 = pack2(wv.x, wv.x);
            unsigned long long w1 = pack2(wv.y, wv.y);
            unsigned long long w2 = pack2(wv.z, wv.z);
            unsigned long long w3 = pack2(wv.w, wv.w);
            acc[0]  = fma2(x01, w0, acc[0]);  acc[1]  = fma2(x23, w0, acc[1]);
            acc[2]  = fma2(x45, w0, acc[2]);  acc[3]  = fma2(x67, w0, acc[3]);
            acc[4]  = fma2(x01, w1, acc[4]);  acc[5]  = fma2(x23, w1, acc[5]);
            acc[6]  = fma2(x45, w1, acc[6]);  acc[7]  = fma2(x67, w1, acc[7]);
            acc[8]  = fma2(x01, w2, acc[8]);  acc[9]  = fma2(x23, w2, acc[9]);
            acc[10] = fma2(x45, w2, acc[10]); acc[11] = fma2(x67, w2, acc[11]);
            acc[12] = fma2(x01, w3, acc[12]); acc[13] = fma2(x23, w3, acc[13]);
            acc[14] = fma2(x45, w3, acc[14]); acc[15] = fma2(x67, w3, acc[15]);
        }

#pragma unroll
        for (int ep = 0; ep < 4; ep++) {
            float lo0, hi0, lo1, hi1, lo2, hi2, lo3, hi3;
            unpack2(acc[0 + ep],  lo0, hi0);
            unpack2(acc[4 + ep],  lo1, hi1);
            unpack2(acc[8 + ep],  lo2, hi2);
            unpack2(acc[12 + ep], lo3, hi3);
            float4 olo = make_float4(lo0 + bv.x, lo1 + bv.y, lo2 + bv.z, lo3 + bv.w);
            float4 ohi = make_float4(hi0 + bv.x, hi1 + bv.y, hi2 + bv.z, hi3 + bv.w);
            int elo = eb + e0 + 2 * ep, ehi = elo + 1;
            *reinterpret_cast<float4*>(out + (size_t)elo * 144 + c0) = olo;
            *reinterpret_cast<float4*>(out + (size_t)ehi * 144 + c0) = ohi;
        }
    }
}

// ---------------------------------------------------------------------------
extern "C" void kernel_launch(void* const* d_in, const int* in_sizes, int n_in,
                              void* d_out, int out_size) {
    const float* atom_fea = (const float*)d_in[0];
    const float* edge_fea = (const float*)d_in[1];
    const int*   sai      = (const int*)  d_in[2];
    const int*   sei      = (const int*)  d_in[3];
    const float* ang      = (const float*)d_in[4];
    const int*   sidx     = (const int*)  d_in[5];
    const float* dist     = (const float*)d_in[6];
    const float* Wf       = (const float*)d_in[7];
    const float* bf       = (const float*)d_in[8];
    const float* Ws       = (const float*)d_in[9];
    const float* bs       = (const float*)d_in[10];
    const float* W1       = (const float*)d_in[11];
    const float* b1       = (const float*)d_in[12];
    const float* W2       = (const float*)d_in[13];
    const float* b2       = (const float*)d_in[14];
    float* out = (float*)d_out;

    const int smB_sz  = (112 * 128 + 112 * XSTR) * 4;
    const int smD1_sz = (240 * 128 + 240 * XSTR) * 4;
    const int smD2_sz = (128 * 144 + 128 * XSTR) * 4;

    static bool attr_done = false;
    if (!attr_done) {
        cudaFuncSetAttribute(kB,  cudaFuncAttributeMaxDynamicSharedMemorySize, smB_sz);
        cudaFuncSetAttribute(kD1, cudaFuncAttributeMaxDynamicSharedMemorySize, smD1_sz);
        cudaFuncSetAttribute(kD2, cudaFuncAttributeMaxDynamicSharedMemorySize, smD2_sz);
        attr_done = true;
    }

    {
        size_t n4 = (size_t)2 * NEg * 64 / 4;
        int blocks = (int)((n4 + 255) / 256);
        kZero<<<blocks, 256>>>();
    }
    kA<<<(NA + 31) / 32, 256>>>(atom_fea, Wf, Ws);
    kB<<<296, 256, smB_sz>>>(edge_fea, Wf, Ws);
    kC<<<2048, 256>>>(sai, sei, ang, sidx, dist, Wf, bf, Ws, bs);
    kD1<<<148, 256, smD1_sz>>>(edge_fea, W1, b1);
    kD2<<<296, 288, smD2_sz>>>(W2, b2, out);
}

// round 7
// speedup vs baseline: 1.9073x; 1.2224x over previous
#include <cuda_runtime.h>
#include <cuda_bf16.h>
#include <mma.h>
#include <math.h>
#include <stdint.h>

using namespace nvcuda;

#define NA   50000
#define NEg  200000
#define NSg  1000000
#define HIDF 128
#define OUTF 144
#define XSTR 68

// Scratch (static device globals; no allocation allowed)
__device__ float g_PA[(size_t)NA * 256];
__device__ float g_PE[(size_t)NEg * 128];
__device__ float g_agg[(size_t)2 * NEg * 64];
__device__ float g_hid[(size_t)NEg * HIDF];
// bf16 hi/lo pre-split weights (plain row-major [K][N])
__device__ __nv_bfloat16 g_W1h[240 * 128], g_W1l[240 * 128];
__device__ __nv_bfloat16 g_W2h[128 * 144], g_W2l[128 * 144];

// ---------------------------------------------------------------------------
// f32x2 packed-math helpers (kept for kB)
// ---------------------------------------------------------------------------
__device__ __forceinline__ unsigned long long pack2(float lo, float hi) {
    unsigned long long r;
    asm("mov.b64 %0, {%1, %2};" : "=l"(r) : "f"(lo), "f"(hi));
    return r;
}
__device__ __forceinline__ void unpack2(unsigned long long v, float& lo, float& hi) {
    asm("mov.b64 {%0, %1}, %2;" : "=f"(lo), "=f"(hi) : "l"(v));
}
__device__ __forceinline__ unsigned long long fma2(unsigned long long a,
                                                   unsigned long long b,
                                                   unsigned long long c) {
    unsigned long long d;
    asm("fma.rn.f32x2 %0, %1, %2, %3;" : "=l"(d) : "l"(a), "l"(b), "l"(c));
    return d;
}
__device__ __forceinline__ void lds_v2u64(unsigned sa, unsigned long long& x0,
                                          unsigned long long& x1) {
    asm("ld.shared.v2.u64 {%0, %1}, [%2];" : "=l"(x0), "=l"(x1) : "r"(sa));
}
__device__ __forceinline__ float silu_f(float v) {
    return v * __fdividef(1.f, 1.f + __expf(-v));
}

// ---------------------------------------------------------------------------
__global__ void kZero() {
    size_t i = (size_t)blockIdx.x * blockDim.x + threadIdx.x;
    size_t n4 = (size_t)2 * NEg * 64 / 4;
    if (i < n4) reinterpret_cast<float4*>(g_agg)[i] = make_float4(0.f, 0.f, 0.f, 0.f);
}

// ---------------------------------------------------------------------------
// kW: split W1/W2 into bf16 hi/lo (plain row-major)
// ---------------------------------------------------------------------------
__global__ void kW(const float* __restrict__ W1, const float* __restrict__ W2) {
    int idx = blockIdx.x * blockDim.x + threadIdx.x;
    if (idx < 240 * 128) {
        float x = W1[idx];
        __nv_bfloat16 h = __float2bfloat16(x);
        __nv_bfloat16 l = __float2bfloat16(x - __bfloat162float(h));
        g_W1h[idx] = h; g_W1l[idx] = l;
    } else if (idx < 240 * 128 + 128 * 144) {
        int j = idx - 240 * 128;
        float x = W2[j];
        __nv_bfloat16 h = __float2bfloat16(x);
        __nv_bfloat16 l = __float2bfloat16(x - __bfloat162float(h));
        g_W2h[j] = h; g_W2l[j] = l;
    }
}

// ---------------------------------------------------------------------------
// Kernel A: per-atom projections (unchanged)
// ---------------------------------------------------------------------------
__global__ __launch_bounds__(256) void kA(const float* __restrict__ atom,
                                          const float* __restrict__ Wf,
                                          const float* __restrict__ Ws) {
    int t = threadIdx.x;
    int m = t >> 6;
    int c = t & 63;
    const float* W = ((m < 2) ? Wf : Ws) + (size_t)(m & 1) * 64 * 64;
    float w[64];
#pragma unroll
    for (int k = 0; k < 64; k++) w[k] = W[k * 64 + c];

    __shared__ float xs[32][64];
    int a0 = blockIdx.x * 32;
    for (int i = t; i < 32 * 64; i += 256) {
        int a = a0 + (i >> 6);
        xs[i >> 6][i & 63] = (a < NA) ? atom[(size_t)a * 64 + (i & 63)] : 0.f;
    }
    __syncthreads();

    for (int j = 0; j < 32; j++) {
        int a = a0 + j;
        if (a >= NA) break;
        const float4* x4 = reinterpret_cast<const float4*>(xs[j]);
        float acc = 0.f;
#pragma unroll
        for (int k4 = 0; k4 < 16; k4++) {
            float4 v = x4[k4];
            acc = fmaf(v.x, w[4 * k4 + 0], acc);
            acc = fmaf(v.y, w[4 * k4 + 1], acc);
            acc = fmaf(v.z, w[4 * k4 + 2], acc);
            acc = fmaf(v.w, w[4 * k4 + 3], acc);
        }
        g_PA[(size_t)a * 256 + t] = acc;
    }
}

// ---------------------------------------------------------------------------
// Kernel B: per-edge projections (SIMT outer-product, unchanged from R5)
// ---------------------------------------------------------------------------
__global__ __launch_bounds__(256) void kB(const float* __restrict__ ef,
                                          const float* __restrict__ Wf,
                                          const float* __restrict__ Ws) {
    extern __shared__ float smB[];
    float* Wc = smB;                 // [112][128]
    float* xs = smB + 112 * 128;     // [112][XSTR]
    int t = threadIdx.x;

    for (int i = t; i < 112 * 128; i += 256) {
        int k = i >> 7, c = i & 127;
        Wc[i] = (c < 64) ? Wf[(size_t)(128 + k) * 64 + c]
                         : Ws[(size_t)(128 + k) * 64 + (c - 64)];
    }

    int cg = t & 31, eg = t >> 5;
    int c0 = cg * 4, e0 = eg * 8;
    unsigned xs_sa = (unsigned)__cvta_generic_to_shared(xs);
    const int ntiles = NEg / 64;
    for (int tile = blockIdx.x; tile < ntiles; tile += gridDim.x) {
        int eb = tile * 64;
        __syncthreads();
        for (int i = t; i < 64 * 28; i += 256) {
            int e = i / 28, kq = i - e * 28;
            float4 v = reinterpret_cast<const float4*>(ef + (size_t)(eb + e) * 112)[kq];
            xs[(4 * kq + 0) * XSTR + e] = v.x;
            xs[(4 * kq + 1) * XSTR + e] = v.y;
            xs[(4 * kq + 2) * XSTR + e] = v.z;
            xs[(4 * kq + 3) * XSTR + e] = v.w;
        }
        __syncthreads();

        unsigned long long acc[16];
#pragma unroll
        for (int i = 0; i < 16; i++) acc[i] = 0ULL;

#pragma unroll 4
        for (int k = 0; k < 112; k++) {
            float4 wv = *reinterpret_cast<const float4*>(Wc + k * 128 + c0);
            unsigned long long x01, x23, x45, x67;
            unsigned base = xs_sa + (unsigned)(k * XSTR + e0) * 4;
            lds_v2u64(base, x01, x23);
            lds_v2u64(base + 16, x45, x67);
            unsigned long long w0 = pack2(wv.x, wv.x);
            unsigned long long w1 = pack2(wv.y, wv.y);
            unsigned long long w2 = pack2(wv.z, wv.z);
            unsigned long long w3 = pack2(wv.w, wv.w);
            acc[0]  = fma2(x01, w0, acc[0]);  acc[1]  = fma2(x23, w0, acc[1]);
            acc[2]  = fma2(x45, w0, acc[2]);  acc[3]  = fma2(x67, w0, acc[3]);
            acc[4]  = fma2(x01, w1, acc[4]);  acc[5]  = fma2(x23, w1, acc[5]);
            acc[6]  = fma2(x45, w1, acc[6]);  acc[7]  = fma2(x67, w1, acc[7]);
            acc[8]  = fma2(x01, w2, acc[8]);  acc[9]  = fma2(x23, w2, acc[9]);
            acc[10] = fma2(x45, w2, acc[10]); acc[11] = fma2(x67, w2, acc[11]);
            acc[12] = fma2(x01, w3, acc[12]); acc[13] = fma2(x23, w3, acc[13]);
            acc[14] = fma2(x45, w3, acc[14]); acc[15] = fma2(x67, w3, acc[15]);
        }

#pragma unroll
        for (int ep = 0; ep < 4; ep++) {
            float lo0, hi0, lo1, hi1, lo2, hi2, lo3, hi3;
            unpack2(acc[0 + ep],  lo0, hi0);
            unpack2(acc[4 + ep],  lo1, hi1);
            unpack2(acc[8 + ep],  lo2, hi2);
            unpack2(acc[12 + ep], lo3, hi3);
            int elo = eb + e0 + 2 * ep, ehi = elo + 1;
            *reinterpret_cast<float4*>(g_PE + (size_t)elo * 128 + c0) =
                make_float4(lo0, lo1, lo2, lo3);
            *reinterpret_cast<float4*>(g_PE + (size_t)ehi * 128 + c0) =
                make_float4(hi0, hi1, hi2, hi3);
        }
    }
}

// ---------------------------------------------------------------------------
// Kernel C (unchanged from R4/R5 best)
// ---------------------------------------------------------------------------
__global__ __launch_bounds__(256) void kC(const int*   __restrict__ sai,
                                          const int*   __restrict__ sei,
                                          const float* __restrict__ ang,
                                          const int*   __restrict__ sidx,
                                          const float* __restrict__ dist,
                                          const float* __restrict__ Wf,
                                          const float* __restrict__ bf,
                                          const float* __restrict__ Ws,
                                          const float* __restrict__ bs) {
    __shared__ float4 sw[16][32];
    int t = threadIdx.x;
    for (int i = t; i < 512; i += 256) {
        int k = i >> 5, l = i & 31;
        float2 wf2 = reinterpret_cast<const float2*>(Wf + (size_t)(240 + k) * 64)[l];
        float2 ws2 = reinterpret_cast<const float2*>(Ws + (size_t)(240 + k) * 64)[l];
        sw[k][l] = make_float4(wf2.x, wf2.y, ws2.x, ws2.y);
    }
    __syncthreads();

    int lane = t & 31;
    float2 bfv = reinterpret_cast<const float2*>(bf)[lane];
    float2 bsv = reinterpret_cast<const float2*>(bs)[lane];

    unsigned wid = ((unsigned)blockIdx.x * blockDim.x + t) >> 5;
    unsigned nwarps = ((unsigned)gridDim.x * blockDim.x) >> 5;
    const unsigned npairs = NSg / 2;

    for (unsigned p = wid; p < npairs; p += nwarps) {
        unsigned s0 = 2 * p, s1 = 2 * p + 1;
        int i00 = sai[2 * s0], i01 = sai[2 * s0 + 1];
        int i10 = sai[2 * s1], i11 = sai[2 * s1 + 1];
        int e0 = sei[s0], e1 = sei[s1];
        int q0 = sidx[s0], q1 = sidx[s1];
        float d0 = dist[e0], d1 = dist[e1];

        const float2* pa00 = reinterpret_cast<const float2*>(g_PA + (size_t)i00 * 256);
        const float2* pa01 = reinterpret_cast<const float2*>(g_PA + (size_t)i01 * 256);
        const float2* pe0  = reinterpret_cast<const float2*>(g_PE + (size_t)e0  * 128);
        const float2* pa10 = reinterpret_cast<const float2*>(g_PA + (size_t)i10 * 256);
        const float2* pa11 = reinterpret_cast<const float2*>(g_PA + (size_t)i11 * 256);
        const float2* pe1  = reinterpret_cast<const float2*>(g_PE + (size_t)e1  * 128);

        float2 A0 = pa00[lane],      B0 = pa01[32 + lane], C0 = pe0[lane];
        float2 D0 = pa00[64 + lane], E0 = pa01[96 + lane], F0 = pe0[32 + lane];
        float2 A1 = pa10[lane],      B1 = pa11[32 + lane], C1 = pe1[lane];
        float2 D1 = pa10[64 + lane], E1 = pa11[96 + lane], F1 = pe1[32 + lane];

        float vf0x = A0.x + B0.x + C0.x + bfv.x;
        float vf0y = A0.y + B0.y + C0.y + bfv.y;
        float vs0x = D0.x + E0.x + F0.x + bsv.x;
        float vs0y = D0.y + E0.y + F0.y + bsv.y;
        float vf1x = A1.x + B1.x + C1.x + bfv.x;
        float vf1y = A1.y + B1.y + C1.y + bfv.y;
        float vs1x = D1.x + E1.x + F1.x + bsv.x;
        float vs1y = D1.y + E1.y + F1.y + bsv.y;

        const float4* ap0 = reinterpret_cast<const float4*>(ang + (size_t)s0 * 16);
        const float4* ap1 = reinterpret_cast<const float4*>(ang + (size_t)s1 * 16);

#pragma unroll
        for (int k4 = 0; k4 < 4; k4++) {
            float4 a0 = ap0[k4];
            float4 a1 = ap1[k4];
            float aa0[4] = {a0.x, a0.y, a0.z, a0.w};
            float aa1[4] = {a1.x, a1.y, a1.z, a1.w};
#pragma unroll
            for (int j = 0; j < 4; j++) {
                float4 w = sw[4 * k4 + j][lane];
                float u0 = aa0[j], u1 = aa1[j];
                vf0x = fmaf(u0, w.x, vf0x);
                vf0y = fmaf(u0, w.y, vf0y);
                vs0x = fmaf(u0, w.z, vs0x);
                vs0y = fmaf(u0, w.w, vs0y);
                vf1x = fmaf(u1, w.x, vf1x);
                vf1y = fmaf(u1, w.y, vf1y);
                vs1x = fmaf(u1, w.z, vs1x);
                vs1y = fmaf(u1, w.w, vs1y);
            }
        }

        float dec0 = __expf(-d0 * d0 * (1.0f / 18.0f));
        float dec1 = __expf(-d1 * d1 * (1.0f / 18.0f));

        float o0x = __fdividef(dec0, 1.f + __expf(-vf0x)) *
                    (fmaxf(vs0x, 0.f) + __logf(1.f + __expf(-fabsf(vs0x))));
        float o0y = __fdividef(dec0, 1.f + __expf(-vf0y)) *
                    (fmaxf(vs0y, 0.f) + __logf(1.f + __expf(-fabsf(vs0y))));
        float o1x = __fdividef(dec1, 1.f + __expf(-vf1x)) *
                    (fmaxf(vs1x, 0.f) + __logf(1.f + __expf(-fabsf(vs1x))));
        float o1y = __fdividef(dec1, 1.f + __expf(-vf1y)) *
                    (fmaxf(vs1y, 0.f) + __logf(1.f + __expf(-fabsf(vs1y))));

        float* dst0 = g_agg + (size_t)q0 * 64 + 2 * lane;
        float* dst1 = g_agg + (size_t)q1 * 64 + 2 * lane;
        atomicAdd(dst0,     o0x);
        atomicAdd(dst0 + 1, o0y);
        atomicAdd(dst1,     o1x);
        atomicAdd(dst1 + 1, o1y);
    }
}

// ---------------------------------------------------------------------------
// kD1w: hid = silu([agg|ef] @ W1 + b1) via WMMA bf16 hi/lo split.
// Tile: 64 edges x 128 cols, K=240 (15 k-steps). 8 warps: 2(M) x 4(N),
// warp tile 32x32 = 2x2 fragments. W resident in smem; A restaged per tile.
// SMEM bytes: WH@0 (240*136*2=65280), WL@65280, AH@130560 (64*248*2=31744),
//             AL@162304; out-staging reuses AH/AL region (64*136*4=34816).
// ---------------------------------------------------------------------------
#define D1_LDW 136
#define D1_LDA 248
#define D1_WH  0
#define D1_WL  65280
#define D1_AH  130560
#define D1_AL  162304
#define D1_ST  130560
#define D1_SMEM 194048

__global__ __launch_bounds__(256) void kD1w(const float* __restrict__ ef,
                                            const float* __restrict__ b1) {
    extern __shared__ char sm[];
    __nv_bfloat16* WH = reinterpret_cast<__nv_bfloat16*>(sm + D1_WH);
    __nv_bfloat16* WL = reinterpret_cast<__nv_bfloat16*>(sm + D1_WL);
    __nv_bfloat16* AH = reinterpret_cast<__nv_bfloat16*>(sm + D1_AH);
    __nv_bfloat16* AL = reinterpret_cast<__nv_bfloat16*>(sm + D1_AL);
    float* ST = reinterpret_cast<float*>(sm + D1_ST);
    __shared__ float b1s[128];

    int t = threadIdx.x;
    for (int i = t; i < 240 * 128; i += 256) {
        int k = i >> 7, n = i & 127;
        WH[k * D1_LDW + n] = g_W1h[i];
        WL[k * D1_LDW + n] = g_W1l[i];
    }
    if (t < 128) b1s[t] = b1[t];

    int w = t >> 5;
    int m0 = (w & 1) * 32, n0 = (w >> 1) * 32;

    const int ntiles = NEg / 64;   // 3125
    for (int tile = blockIdx.x; tile < ntiles; tile += gridDim.x) {
        int eb = tile * 64;
        __syncthreads();   // prev epilogue staging reads done
        // stage A (fp32 -> bf16 hi/lo)
        for (int cid = t; cid < 64 * 60; cid += 256) {
            int e = cid / 60, q = cid - e * 60;
            int k0 = q * 4;
            const float* src = (q < 32)
                ? (g_agg + (size_t)(eb + e) * 128 + k0)
                : (ef + (size_t)(eb + e) * 112 + (k0 - 128));
            float4 v = *reinterpret_cast<const float4*>(src);
            __nv_bfloat16 h0 = __float2bfloat16(v.x), h1 = __float2bfloat16(v.y);
            __nv_bfloat16 h2 = __float2bfloat16(v.z), h3 = __float2bfloat16(v.w);
            __nv_bfloat16 l0 = __float2bfloat16(v.x - __bfloat162float(h0));
            __nv_bfloat16 l1 = __float2bfloat16(v.y - __bfloat162float(h1));
            __nv_bfloat16 l2 = __float2bfloat16(v.z - __bfloat162float(h2));
            __nv_bfloat16 l3 = __float2bfloat16(v.w - __bfloat162float(h3));
            int off = e * D1_LDA + k0;
            *reinterpret_cast<__nv_bfloat162*>(AH + off)     = __nv_bfloat162(h0, h1);
            *reinterpret_cast<__nv_bfloat162*>(AH + off + 2) = __nv_bfloat162(h2, h3);
            *reinterpret_cast<__nv_bfloat162*>(AL + off)     = __nv_bfloat162(l0, l1);
            *reinterpret_cast<__nv_bfloat162*>(AL + off + 2) = __nv_bfloat162(l2, l3);
        }
        __syncthreads();

        wmma::fragment<wmma::accumulator, 16, 16, 16, float> acc[2][2];
#pragma unroll
        for (int mi = 0; mi < 2; mi++)
#pragma unroll
            for (int ni = 0; ni < 2; ni++) wmma::fill_fragment(acc[mi][ni], 0.0f);

        for (int ks = 0; ks < 15; ks++) {
            wmma::fragment<wmma::matrix_a, 16, 16, 16, __nv_bfloat16, wmma::row_major> ah[2], al[2];
            wmma::fragment<wmma::matrix_b, 16, 16, 16, __nv_bfloat16, wmma::row_major> bh[2], bl[2];
#pragma unroll
            for (int mi = 0; mi < 2; mi++) {
                const __nv_bfloat16* pa = AH + (m0 + 16 * mi) * D1_LDA + ks * 16;
                const __nv_bfloat16* pl = AL + (m0 + 16 * mi) * D1_LDA + ks * 16;
                wmma::load_matrix_sync(ah[mi], pa, D1_LDA);
                wmma::load_matrix_sync(al[mi], pl, D1_LDA);
            }
#pragma unroll
            for (int ni = 0; ni < 2; ni++) {
                const __nv_bfloat16* pb = WH + (ks * 16) * D1_LDW + n0 + 16 * ni;
                const __nv_bfloat16* ql = WL + (ks * 16) * D1_LDW + n0 + 16 * ni;
                wmma::load_matrix_sync(bh[ni], pb, D1_LDW);
                wmma::load_matrix_sync(bl[ni], ql, D1_LDW);
            }
#pragma unroll
            for (int mi = 0; mi < 2; mi++)
#pragma unroll
                for (int ni = 0; ni < 2; ni++) {
                    wmma::mma_sync(acc[mi][ni], ah[mi], bh[ni], acc[mi][ni]);
                    wmma::mma_sync(acc[mi][ni], ah[mi], bl[ni], acc[mi][ni]);
                    wmma::mma_sync(acc[mi][ni], al[mi], bh[ni], acc[mi][ni]);
                }
        }
        __syncthreads();   // all A reads done before staging overwrite
#pragma unroll
        for (int mi = 0; mi < 2; mi++)
#pragma unroll
            for (int ni = 0; ni < 2; ni++)
                wmma::store_matrix_sync(ST + (m0 + 16 * mi) * D1_LDW + n0 + 16 * ni,
                                        acc[mi][ni], D1_LDW, wmma::mem_row_major);
        __syncthreads();
        // epilogue: bias + silu -> g_hid
        for (int cid = t; cid < 64 * 32; cid += 256) {
            int e = cid >> 5, cq = cid & 31;
            int c = cq * 4;
            float4 v = *reinterpret_cast<const float4*>(ST + e * D1_LDW + c);
            float4 o;
            o.x = silu_f(v.x + b1s[c + 0]);
            o.y = silu_f(v.y + b1s[c + 1]);
            o.z = silu_f(v.z + b1s[c + 2]);
            o.w = silu_f(v.w + b1s[c + 3]);
            *reinterpret_cast<float4*>(g_hid + (size_t)(eb + e) * 128 + c) = o;
        }
    }
}

// ---------------------------------------------------------------------------
// kD2w: out = hid @ W2 + b2 via WMMA bf16 hi/lo split.
// Tile: 64 edges x 144 cols, K=128 (8 k-steps). 8 warps: w&3 -> m-frag (16
// rows), w>>2 -> n-group (frags 0-4 / 5-8). W resident; A restaged per tile.
// SMEM: WH@0 (128*152*2=38912), WL@38912, AH@77824 (64*136*2=17408),
//       AL@95232, ST@112640 (64*144*4=36864). total 149504
// ---------------------------------------------------------------------------
#define D2_LDW 152
#define D2_LDA 136
#define D2_WH  0
#define D2_WL  38912
#define D2_AH  77824
#define D2_AL  95232
#define D2_ST  112640
#define D2_SMEM 149504

__global__ __launch_bounds__(256) void kD2w(const float* __restrict__ b2,
                                            float* __restrict__ out) {
    extern __shared__ char sm[];
    __nv_bfloat16* WH = reinterpret_cast<__nv_bfloat16*>(sm + D2_WH);
    __nv_bfloat16* WL = reinterpret_cast<__nv_bfloat16*>(sm + D2_WL);
    __nv_bfloat16* AH = reinterpret_cast<__nv_bfloat16*>(sm + D2_AH);
    __nv_bfloat16* AL = reinterpret_cast<__nv_bfloat16*>(sm + D2_AL);
    float* ST = reinterpret_cast<float*>(sm + D2_ST);
    __shared__ float b2s[144];

    int t = threadIdx.x;
    for (int i = t; i < 128 * 144; i += 256) {
        int k = i / 144, n = i - k * 144;
        WH[k * D2_LDW + n] = g_W2h[i];
        WL[k * D2_LDW + n] = g_W2l[i];
    }
    if (t < 144) b2s[t] = b2[t];

    int w = t >> 5;
    int m0 = (w & 3) * 16;
    int nh = w >> 2;
    int nfr = nh ? 4 : 5;
    int nbase = nh ? 80 : 0;

    const int ntiles = NEg / 64;
    for (int tile = blockIdx.x; tile < ntiles; tile += gridDim.x) {
        int eb = tile * 64;
        __syncthreads();
        // stage A from g_hid
        for (int cid = t; cid < 64 * 32; cid += 256) {
            int e = cid >> 5, q = cid & 31;
            int k0 = q * 4;
            float4 v = *reinterpret_cast<const float4*>(g_hid + (size_t)(eb + e) * 128 + k0);
            __nv_bfloat16 h0 = __float2bfloat16(v.x), h1 = __float2bfloat16(v.y);
            __nv_bfloat16 h2 = __float2bfloat16(v.z), h3 = __float2bfloat16(v.w);
            __nv_bfloat16 l0 = __float2bfloat16(v.x - __bfloat162float(h0));
            __nv_bfloat16 l1 = __float2bfloat16(v.y - __bfloat162float(h1));
            __nv_bfloat16 l2 = __float2bfloat16(v.z - __bfloat162float(h2));
            __nv_bfloat16 l3 = __float2bfloat16(v.w - __bfloat162float(h3));
            int off = e * D2_LDA + k0;
            *reinterpret_cast<__nv_bfloat162*>(AH + off)     = __nv_bfloat162(h0, h1);
            *reinterpret_cast<__nv_bfloat162*>(AH + off + 2) = __nv_bfloat162(h2, h3);
            *reinterpret_cast<__nv_bfloat162*>(AL + off)     = __nv_bfloat162(l0, l1);
            *reinterpret_cast<__nv_bfloat162*>(AL + off + 2) = __nv_bfloat162(l2, l3);
        }
        __syncthreads();

        wmma::fragment<wmma::accumulator, 16, 16, 16, float> acc[5];
        for (int ni = 0; ni < 5; ni++) wmma::fill_fragment(acc[ni], 0.0f);

        for (int ks = 0; ks < 8; ks++) {
            wmma::fragment<wmma::matrix_a, 16, 16, 16, __nv_bfloat16, wmma::row_major> ah, al;
            wmma::load_matrix_sync(ah, AH + m0 * D2_LDA + ks * 16, D2_LDA);
            wmma::load_matrix_sync(al, AL + m0 * D2_LDA + ks * 16, D2_LDA);
            for (int ni = 0; ni < nfr; ni++) {
                int n0 = nbase + ni * 16;
                wmma::fragment<wmma::matrix_b, 16, 16, 16, __nv_bfloat16, wmma::row_major> bh, bl;
                wmma::load_matrix_sync(bh, WH + (ks * 16) * D2_LDW + n0, D2_LDW);
                wmma::load_matrix_sync(bl, WL + (ks * 16) * D2_LDW + n0, D2_LDW);
                wmma::mma_sync(acc[ni], ah, bh, acc[ni]);
                wmma::mma_sync(acc[ni], ah, bl, acc[ni]);
                wmma::mma_sync(acc[ni], al, bh, acc[ni]);
            }
        }
        __syncthreads();
        for (int ni = 0; ni < nfr; ni++)
            wmma::store_matrix_sync(ST + m0 * 144 + nbase + ni * 16,
                                    acc[ni], 144, wmma::mem_row_major);
        __syncthreads();
        for (int cid = t; cid < 64 * 36; cid += 256) {
            int e = cid / 36, cq = cid - e * 36;
            int c = cq * 4;
            float4 v = *reinterpret_cast<const float4*>(ST + e * 144 + c);
            float4 o;
            o.x = v.x + b2s[c + 0];
            o.y = v.y + b2s[c + 1];
            o.z = v.z + b2s[c + 2];
            o.w = v.w + b2s[c + 3];
            *reinterpret_cast<float4*>(out + (size_t)(eb + e) * 144 + c) = o;
        }
    }
}

// ---------------------------------------------------------------------------
extern "C" void kernel_launch(void* const* d_in, const int* in_sizes, int n_in,
                              void* d_out, int out_size) {
    const float* atom_fea = (const float*)d_in[0];
    const float* edge_fea = (const float*)d_in[1];
    const int*   sai      = (const int*)  d_in[2];
    const int*   sei      = (const int*)  d_in[3];
    const float* ang      = (const float*)d_in[4];
    const int*   sidx     = (const int*)  d_in[5];
    const float* dist     = (const float*)d_in[6];
    const float* Wf       = (const float*)d_in[7];
    const float* bf       = (const float*)d_in[8];
    const float* Ws       = (const float*)d_in[9];
    const float* bs       = (const float*)d_in[10];
    const float* W1       = (const float*)d_in[11];
    const float* b1       = (const float*)d_in[12];
    const float* W2       = (const float*)d_in[13];
    const float* b2       = (const float*)d_in[14];
    float* out = (float*)d_out;

    const int smB_sz = (112 * 128 + 112 * XSTR) * 4;

    static bool attr_done = false;
    if (!attr_done) {
        cudaFuncSetAttribute(kB,   cudaFuncAttributeMaxDynamicSharedMemorySize, smB_sz);
        cudaFuncSetAttribute(kD1w, cudaFuncAttributeMaxDynamicSharedMemorySize, D1_SMEM);
        cudaFuncSetAttribute(kD2w, cudaFuncAttributeMaxDynamicSharedMemorySize, D2_SMEM);
        attr_done = true;
    }

    {
        size_t n4 = (size_t)2 * NEg * 64 / 4;
        int blocks = (int)((n4 + 255) / 256);
        kZero<<<blocks, 256>>>();
    }
    kW<<<192, 256>>>(W1, W2);
    kA<<<(NA + 31) / 32, 256>>>(atom_fea, Wf, Ws);
    kB<<<296, 256, smB_sz>>>(edge_fea, Wf, Ws);
    kC<<<2048, 256>>>(sai, sei, ang, sidx, dist, Wf, bf, Ws, bs);
    kD1w<<<148, 256, D1_SMEM>>>(edge_fea, b1);
    kD2w<<<148, 256, D2_SMEM>>>(b2, out);
}

// round 8
// speedup vs baseline: 2.0011x; 1.0491x over previous
#include <cuda_runtime.h>
#include <cuda_bf16.h>
#include <mma.h>
#include <math.h>
#include <stdint.h>

using namespace nvcuda;

#define NA   50000
#define NEg  200000
#define NSg  1000000
#define HIDF 128
#define OUTF 144

// Scratch (static device globals; no allocation allowed)
__device__ float g_PA[(size_t)NA * 256];
__device__ float g_PE[(size_t)NEg * 128];
__device__ float g_agg[(size_t)2 * NEg * 64];
__device__ float g_hid[(size_t)NEg * HIDF];
// bf16 hi/lo pre-split weights (plain row-major [K][N])
__device__ __nv_bfloat16 g_W1h[240 * 128], g_W1l[240 * 128];
__device__ __nv_bfloat16 g_W2h[128 * 144], g_W2l[128 * 144];
__device__ __nv_bfloat16 g_WBh[112 * 128], g_WBl[112 * 128];   // kB weights

__device__ __forceinline__ float silu_f(float v) {
    return v * __fdividef(1.f, 1.f + __expf(-v));
}

// ---------------------------------------------------------------------------
__global__ void kZero() {
    size_t i = (size_t)blockIdx.x * blockDim.x + threadIdx.x;
    size_t n4 = (size_t)2 * NEg * 64 / 4;
    if (i < n4) reinterpret_cast<float4*>(g_agg)[i] = make_float4(0.f, 0.f, 0.f, 0.f);
}

// ---------------------------------------------------------------------------
// kW: split W1/W2/WB(=cat(Wf,Ws) rows 128..239) into bf16 hi/lo
// ---------------------------------------------------------------------------
__global__ void kW(const float* __restrict__ W1, const float* __restrict__ W2,
                   const float* __restrict__ Wf, const float* __restrict__ Ws) {
    int idx = blockIdx.x * blockDim.x + threadIdx.x;
    if (idx < 240 * 128) {
        float x = W1[idx];
        __nv_bfloat16 h = __float2bfloat16(x);
        __nv_bfloat16 l = __float2bfloat16(x - __bfloat162float(h));
        g_W1h[idx] = h; g_W1l[idx] = l;
    } else if (idx < 240 * 128 + 128 * 144) {
        int j = idx - 240 * 128;
        float x = W2[j];
        __nv_bfloat16 h = __float2bfloat16(x);
        __nv_bfloat16 l = __float2bfloat16(x - __bfloat162float(h));
        g_W2h[j] = h; g_W2l[j] = l;
    } else if (idx < 240 * 128 + 128 * 144 + 112 * 128) {
        int j = idx - 240 * 128 - 128 * 144;
        int k = j >> 7, c = j & 127;
        float x = (c < 64) ? Wf[(size_t)(128 + k) * 64 + c]
                           : Ws[(size_t)(128 + k) * 64 + (c - 64)];
        __nv_bfloat16 h = __float2bfloat16(x);
        __nv_bfloat16 l = __float2bfloat16(x - __bfloat162float(h));
        g_WBh[j] = h; g_WBl[j] = l;
    }
}

// ---------------------------------------------------------------------------
// Kernel A: per-atom projections (unchanged)
// ---------------------------------------------------------------------------
__global__ __launch_bounds__(256) void kA(const float* __restrict__ atom,
                                          const float* __restrict__ Wf,
                                          const float* __restrict__ Ws) {
    int t = threadIdx.x;
    int m = t >> 6;
    int c = t & 63;
    const float* W = ((m < 2) ? Wf : Ws) + (size_t)(m & 1) * 64 * 64;
    float w[64];
#pragma unroll
    for (int k = 0; k < 64; k++) w[k] = W[k * 64 + c];

    __shared__ float xs[32][64];
    int a0 = blockIdx.x * 32;
    for (int i = t; i < 32 * 64; i += 256) {
        int a = a0 + (i >> 6);
        xs[i >> 6][i & 63] = (a < NA) ? atom[(size_t)a * 64 + (i & 63)] : 0.f;
    }
    __syncthreads();

    for (int j = 0; j < 32; j++) {
        int a = a0 + j;
        if (a >= NA) break;
        const float4* x4 = reinterpret_cast<const float4*>(xs[j]);
        float acc = 0.f;
#pragma unroll
        for (int k4 = 0; k4 < 16; k4++) {
            float4 v = x4[k4];
            acc = fmaf(v.x, w[4 * k4 + 0], acc);
            acc = fmaf(v.y, w[4 * k4 + 1], acc);
            acc = fmaf(v.z, w[4 * k4 + 2], acc);
            acc = fmaf(v.w, w[4 * k4 + 3], acc);
        }
        g_PA[(size_t)a * 256 + t] = acc;
    }
}

// ---------------------------------------------------------------------------
// kBw: PE = ef @ WB via WMMA bf16 hi/lo split.
// Tile: 128 edges x 128 cols, K=112 (7 k-steps). 8 warps: 4(M) x 2(N),
// warp tile 32x64 = 2x4 fragments. W resident; A restaged per tile.
// SMEM: WH@0 (112*136*2=30464), WL@30464, AH@60928 (128*120*2=30720),
//       AL@91648, ST@122368 (128*136*4=69632). total 192000
// ---------------------------------------------------------------------------
#define B_LDW 136
#define B_LDA 120
#define B_WH  0
#define B_WL  30464
#define B_AH  60928
#define B_AL  91648
#define B_ST  122368
#define B_SMEM 192000

__global__ __launch_bounds__(256) void kBw(const float* __restrict__ ef) {
    extern __shared__ char sm[];
    __nv_bfloat16* WH = reinterpret_cast<__nv_bfloat16*>(sm + B_WH);
    __nv_bfloat16* WL = reinterpret_cast<__nv_bfloat16*>(sm + B_WL);
    __nv_bfloat16* AH = reinterpret_cast<__nv_bfloat16*>(sm + B_AH);
    __nv_bfloat16* AL = reinterpret_cast<__nv_bfloat16*>(sm + B_AL);
    float* ST = reinterpret_cast<float*>(sm + B_ST);

    int t = threadIdx.x;
    for (int i = t; i < 112 * 128; i += 256) {
        int k = i >> 7, n = i & 127;
        WH[k * B_LDW + n] = g_WBh[i];
        WL[k * B_LDW + n] = g_WBl[i];
    }

    int w = t >> 5;
    int m0 = (w & 3) * 32, n0 = (w >> 2) * 64;

    const int ntiles = (NEg + 127) / 128;   // 1563
    for (int tile = blockIdx.x; tile < ntiles; tile += gridDim.x) {
        int eb = tile * 128;
        __syncthreads();
        // stage A (fp32 -> bf16 hi/lo), 128 rows x 28 k-quads
        for (int cid = t; cid < 128 * 28; cid += 256) {
            int e = cid / 28, q = cid - e * 28;
            int k0 = q * 4;
            int row = eb + e; if (row >= NEg) row = NEg - 1;
            float4 v = *reinterpret_cast<const float4*>(ef + (size_t)row * 112 + k0);
            __nv_bfloat16 h0 = __float2bfloat16(v.x), h1 = __float2bfloat16(v.y);
            __nv_bfloat16 h2 = __float2bfloat16(v.z), h3 = __float2bfloat16(v.w);
            __nv_bfloat16 l0 = __float2bfloat16(v.x - __bfloat162float(h0));
            __nv_bfloat16 l1 = __float2bfloat16(v.y - __bfloat162float(h1));
            __nv_bfloat16 l2 = __float2bfloat16(v.z - __bfloat162float(h2));
            __nv_bfloat16 l3 = __float2bfloat16(v.w - __bfloat162float(h3));
            int off = e * B_LDA + k0;
            *reinterpret_cast<__nv_bfloat162*>(AH + off)     = __nv_bfloat162(h0, h1);
            *reinterpret_cast<__nv_bfloat162*>(AH + off + 2) = __nv_bfloat162(h2, h3);
            *reinterpret_cast<__nv_bfloat162*>(AL + off)     = __nv_bfloat162(l0, l1);
            *reinterpret_cast<__nv_bfloat162*>(AL + off + 2) = __nv_bfloat162(l2, l3);
        }
        __syncthreads();

        wmma::fragment<wmma::accumulator, 16, 16, 16, float> acc[2][4];
#pragma unroll
        for (int mi = 0; mi < 2; mi++)
#pragma unroll
            for (int ni = 0; ni < 4; ni++) wmma::fill_fragment(acc[mi][ni], 0.0f);

        for (int ks = 0; ks < 7; ks++) {
            wmma::fragment<wmma::matrix_a, 16, 16, 16, __nv_bfloat16, wmma::row_major> ah[2], al[2];
#pragma unroll
            for (int mi = 0; mi < 2; mi++) {
                wmma::load_matrix_sync(ah[mi], AH + (m0 + 16 * mi) * B_LDA + ks * 16, B_LDA);
                wmma::load_matrix_sync(al[mi], AL + (m0 + 16 * mi) * B_LDA + ks * 16, B_LDA);
            }
#pragma unroll
            for (int ni = 0; ni < 4; ni++) {
                int nc = n0 + 16 * ni;
                wmma::fragment<wmma::matrix_b, 16, 16, 16, __nv_bfloat16, wmma::row_major> bh, bl;
                wmma::load_matrix_sync(bh, WH + (ks * 16) * B_LDW + nc, B_LDW);
                wmma::load_matrix_sync(bl, WL + (ks * 16) * B_LDW + nc, B_LDW);
#pragma unroll
                for (int mi = 0; mi < 2; mi++) {
                    wmma::mma_sync(acc[mi][ni], ah[mi], bh, acc[mi][ni]);
                    wmma::mma_sync(acc[mi][ni], ah[mi], bl, acc[mi][ni]);
                    wmma::mma_sync(acc[mi][ni], al[mi], bh, acc[mi][ni]);
                }
            }
        }
        __syncthreads();
#pragma unroll
        for (int mi = 0; mi < 2; mi++)
#pragma unroll
            for (int ni = 0; ni < 4; ni++)
                wmma::store_matrix_sync(ST + (m0 + 16 * mi) * B_LDW + n0 + 16 * ni,
                                        acc[mi][ni], B_LDW, wmma::mem_row_major);
        __syncthreads();
        // epilogue -> g_PE
        for (int cid = t; cid < 128 * 32; cid += 256) {
            int e = cid >> 5, cq = cid & 31;
            int c = cq * 4;
            if (eb + e < NEg) {
                float4 v = *reinterpret_cast<const float4*>(ST + e * B_LDW + c);
                *reinterpret_cast<float4*>(g_PE + (size_t)(eb + e) * 128 + c) = v;
            }
        }
    }
}

// ---------------------------------------------------------------------------
// Kernel C (unchanged from R4/R5 best)
// ---------------------------------------------------------------------------
__global__ __launch_bounds__(256) void kC(const int*   __restrict__ sai,
                                          const int*   __restrict__ sei,
                                          const float* __restrict__ ang,
                                          const int*   __restrict__ sidx,
                                          const float* __restrict__ dist,
                                          const float* __restrict__ Wf,
                                          const float* __restrict__ bf,
                                          const float* __restrict__ Ws,
                                          const float* __restrict__ bs) {
    __shared__ float4 sw[16][32];
    int t = threadIdx.x;
    for (int i = t; i < 512; i += 256) {
        int k = i >> 5, l = i & 31;
        float2 wf2 = reinterpret_cast<const float2*>(Wf + (size_t)(240 + k) * 64)[l];
        float2 ws2 = reinterpret_cast<const float2*>(Ws + (size_t)(240 + k) * 64)[l];
        sw[k][l] = make_float4(wf2.x, wf2.y, ws2.x, ws2.y);
    }
    __syncthreads();

    int lane = t & 31;
    float2 bfv = reinterpret_cast<const float2*>(bf)[lane];
    float2 bsv = reinterpret_cast<const float2*>(bs)[lane];

    unsigned wid = ((unsigned)blockIdx.x * blockDim.x + t) >> 5;
    unsigned nwarps = ((unsigned)gridDim.x * blockDim.x) >> 5;
    const unsigned npairs = NSg / 2;

    for (unsigned p = wid; p < npairs; p += nwarps) {
        unsigned s0 = 2 * p, s1 = 2 * p + 1;
        int i00 = sai[2 * s0], i01 = sai[2 * s0 + 1];
        int i10 = sai[2 * s1], i11 = sai[2 * s1 + 1];
        int e0 = sei[s0], e1 = sei[s1];
        int q0 = sidx[s0], q1 = sidx[s1];
        float d0 = dist[e0], d1 = dist[e1];

        const float2* pa00 = reinterpret_cast<const float2*>(g_PA + (size_t)i00 * 256);
        const float2* pa01 = reinterpret_cast<const float2*>(g_PA + (size_t)i01 * 256);
        const float2* pe0  = reinterpret_cast<const float2*>(g_PE + (size_t)e0  * 128);
        const float2* pa10 = reinterpret_cast<const float2*>(g_PA + (size_t)i10 * 256);
        const float2* pa11 = reinterpret_cast<const float2*>(g_PA + (size_t)i11 * 256);
        const float2* pe1  = reinterpret_cast<const float2*>(g_PE + (size_t)e1  * 128);

        float2 A0 = pa00[lane],      B0 = pa01[32 + lane], C0 = pe0[lane];
        float2 D0 = pa00[64 + lane], E0 = pa01[96 + lane], F0 = pe0[32 + lane];
        float2 A1 = pa10[lane],      B1 = pa11[32 + lane], C1 = pe1[lane];
        float2 D1 = pa10[64 + lane], E1 = pa11[96 + lane], F1 = pe1[32 + lane];

        float vf0x = A0.x + B0.x + C0.x + bfv.x;
        float vf0y = A0.y + B0.y + C0.y + bfv.y;
        float vs0x = D0.x + E0.x + F0.x + bsv.x;
        float vs0y = D0.y + E0.y + F0.y + bsv.y;
        float vf1x = A1.x + B1.x + C1.x + bfv.x;
        float vf1y = A1.y + B1.y + C1.y + bfv.y;
        float vs1x = D1.x + E1.x + F1.x + bsv.x;
        float vs1y = D1.y + E1.y + F1.y + bsv.y;

        const float4* ap0 = reinterpret_cast<const float4*>(ang + (size_t)s0 * 16);
        const float4* ap1 = reinterpret_cast<const float4*>(ang + (size_t)s1 * 16);

#pragma unroll
        for (int k4 = 0; k4 < 4; k4++) {
            float4 a0 = ap0[k4];
            float4 a1 = ap1[k4];
            float aa0[4] = {a0.x, a0.y, a0.z, a0.w};
            float aa1[4] = {a1.x, a1.y, a1.z, a1.w};
#pragma unroll
            for (int j = 0; j < 4; j++) {
                float4 w = sw[4 * k4 + j][lane];
                float u0 = aa0[j], u1 = aa1[j];
                vf0x = fmaf(u0, w.x, vf0x);
                vf0y = fmaf(u0, w.y, vf0y);
                vs0x = fmaf(u0, w.z, vs0x);
                vs0y = fmaf(u0, w.w, vs0y);
                vf1x = fmaf(u1, w.x, vf1x);
                vf1y = fmaf(u1, w.y, vf1y);
                vs1x = fmaf(u1, w.z, vs1x);
                vs1y = fmaf(u1, w.w, vs1y);
            }
        }

        float dec0 = __expf(-d0 * d0 * (1.0f / 18.0f));
        float dec1 = __expf(-d1 * d1 * (1.0f / 18.0f));

        float o0x = __fdividef(dec0, 1.f + __expf(-vf0x)) *
                    (fmaxf(vs0x, 0.f) + __logf(1.f + __expf(-fabsf(vs0x))));
        float o0y = __fdividef(dec0, 1.f + __expf(-vf0y)) *
                    (fmaxf(vs0y, 0.f) + __logf(1.f + __expf(-fabsf(vs0y))));
        float o1x = __fdividef(dec1, 1.f + __expf(-vf1x)) *
                    (fmaxf(vs1x, 0.f) + __logf(1.f + __expf(-fabsf(vs1x))));
        float o1y = __fdividef(dec1, 1.f + __expf(-vf1y)) *
                    (fmaxf(vs1y, 0.f) + __logf(1.f + __expf(-fabsf(vs1y))));

        float* dst0 = g_agg + (size_t)q0 * 64 + 2 * lane;
        float* dst1 = g_agg + (size_t)q1 * 64 + 2 * lane;
        atomicAdd(dst0,     o0x);
        atomicAdd(dst0 + 1, o0y);
        atomicAdd(dst1,     o1x);
        atomicAdd(dst1 + 1, o1y);
    }
}

// ---------------------------------------------------------------------------
// kD1w: hid = silu([agg|ef] @ W1 + b1) via WMMA bf16 hi/lo (unchanged R7)
// ---------------------------------------------------------------------------
#define D1_LDW 136
#define D1_LDA 248
#define D1_WH  0
#define D1_WL  65280
#define D1_AH  130560
#define D1_AL  162304
#define D1_ST  130560
#define D1_SMEM 194048

__global__ __launch_bounds__(256) void kD1w(const float* __restrict__ ef,
                                            const float* __restrict__ b1) {
    extern __shared__ char sm[];
    __nv_bfloat16* WH = reinterpret_cast<__nv_bfloat16*>(sm + D1_WH);
    __nv_bfloat16* WL = reinterpret_cast<__nv_bfloat16*>(sm + D1_WL);
    __nv_bfloat16* AH = reinterpret_cast<__nv_bfloat16*>(sm + D1_AH);
    __nv_bfloat16* AL = reinterpret_cast<__nv_bfloat16*>(sm + D1_AL);
    float* ST = reinterpret_cast<float*>(sm + D1_ST);
    __shared__ float b1s[128];

    int t = threadIdx.x;
    for (int i = t; i < 240 * 128; i += 256) {
        int k = i >> 7, n = i & 127;
        WH[k * D1_LDW + n] = g_W1h[i];
        WL[k * D1_LDW + n] = g_W1l[i];
    }
    if (t < 128) b1s[t] = b1[t];

    int w = t >> 5;
    int m0 = (w & 1) * 32, n0 = (w >> 1) * 32;

    const int ntiles = NEg / 64;   // 3125
    for (int tile = blockIdx.x; tile < ntiles; tile += gridDim.x) {
        int eb = tile * 64;
        __syncthreads();
        for (int cid = t; cid < 64 * 60; cid += 256) {
            int e = cid / 60, q = cid - e * 60;
            int k0 = q * 4;
            const float* src = (q < 32)
                ? (g_agg + (size_t)(eb + e) * 128 + k0)
                : (ef + (size_t)(eb + e) * 112 + (k0 - 128));
            float4 v = *reinterpret_cast<const float4*>(src);
            __nv_bfloat16 h0 = __float2bfloat16(v.x), h1 = __float2bfloat16(v.y);
            __nv_bfloat16 h2 = __float2bfloat16(v.z), h3 = __float2bfloat16(v.w);
            __nv_bfloat16 l0 = __float2bfloat16(v.x - __bfloat162float(h0));
            __nv_bfloat16 l1 = __float2bfloat16(v.y - __bfloat162float(h1));
            __nv_bfloat16 l2 = __float2bfloat16(v.z - __bfloat162float(h2));
            __nv_bfloat16 l3 = __float2bfloat16(v.w - __bfloat162float(h3));
            int off = e * D1_LDA + k0;
            *reinterpret_cast<__nv_bfloat162*>(AH + off)     = __nv_bfloat162(h0, h1);
            *reinterpret_cast<__nv_bfloat162*>(AH + off + 2) = __nv_bfloat162(h2, h3);
            *reinterpret_cast<__nv_bfloat162*>(AL + off)     = __nv_bfloat162(l0, l1);
            *reinterpret_cast<__nv_bfloat162*>(AL + off + 2) = __nv_bfloat162(l2, l3);
        }
        __syncthreads();

        wmma::fragment<wmma::accumulator, 16, 16, 16, float> acc[2][2];
#pragma unroll
        for (int mi = 0; mi < 2; mi++)
#pragma unroll
            for (int ni = 0; ni < 2; ni++) wmma::fill_fragment(acc[mi][ni], 0.0f);

        for (int ks = 0; ks < 15; ks++) {
            wmma::fragment<wmma::matrix_a, 16, 16, 16, __nv_bfloat16, wmma::row_major> ah[2], al[2];
            wmma::fragment<wmma::matrix_b, 16, 16, 16, __nv_bfloat16, wmma::row_major> bh[2], bl[2];
#pragma unroll
            for (int mi = 0; mi < 2; mi++) {
                wmma::load_matrix_sync(ah[mi], AH + (m0 + 16 * mi) * D1_LDA + ks * 16, D1_LDA);
                wmma::load_matrix_sync(al[mi], AL + (m0 + 16 * mi) * D1_LDA + ks * 16, D1_LDA);
            }
#pragma unroll
            for (int ni = 0; ni < 2; ni++) {
                wmma::load_matrix_sync(bh[ni], WH + (ks * 16) * D1_LDW + n0 + 16 * ni, D1_LDW);
                wmma::load_matrix_sync(bl[ni], WL + (ks * 16) * D1_LDW + n0 + 16 * ni, D1_LDW);
            }
#pragma unroll
            for (int mi = 0; mi < 2; mi++)
#pragma unroll
                for (int ni = 0; ni < 2; ni++) {
                    wmma::mma_sync(acc[mi][ni], ah[mi], bh[ni], acc[mi][ni]);
                    wmma::mma_sync(acc[mi][ni], ah[mi], bl[ni], acc[mi][ni]);
                    wmma::mma_sync(acc[mi][ni], al[mi], bh[ni], acc[mi][ni]);
                }
        }
        __syncthreads();
#pragma unroll
        for (int mi = 0; mi < 2; mi++)
#pragma unroll
            for (int ni = 0; ni < 2; ni++)
                wmma::store_matrix_sync(ST + (m0 + 16 * mi) * D1_LDW + n0 + 16 * ni,
                                        acc[mi][ni], D1_LDW, wmma::mem_row_major);
        __syncthreads();
        for (int cid = t; cid < 64 * 32; cid += 256) {
            int e = cid >> 5, cq = cid & 31;
            int c = cq * 4;
            float4 v = *reinterpret_cast<const float4*>(ST + e * D1_LDW + c);
            float4 o;
            o.x = silu_f(v.x + b1s[c + 0]);
            o.y = silu_f(v.y + b1s[c + 1]);
            o.z = silu_f(v.z + b1s[c + 2]);
            o.w = silu_f(v.w + b1s[c + 3]);
            *reinterpret_cast<float4*>(g_hid + (size_t)(eb + e) * 128 + c) = o;
        }
    }
}

// ---------------------------------------------------------------------------
// kD2w: out = hid @ W2 + b2 via WMMA bf16 hi/lo (unchanged R7)
// ---------------------------------------------------------------------------
#define D2_LDW 152
#define D2_LDA 136
#define D2_WH  0
#define D2_WL  38912
#define D2_AH  77824
#define D2_AL  95232
#define D2_ST  112640
#define D2_SMEM 149504

__global__ __launch_bounds__(256) void kD2w(const float* __restrict__ b2,
                                            float* __restrict__ out) {
    extern __shared__ char sm[];
    __nv_bfloat16* WH = reinterpret_cast<__nv_bfloat16*>(sm + D2_WH);
    __nv_bfloat16* WL = reinterpret_cast<__nv_bfloat16*>(sm + D2_WL);
    __nv_bfloat16* AH = reinterpret_cast<__nv_bfloat16*>(sm + D2_AH);
    __nv_bfloat16* AL = reinterpret_cast<__nv_bfloat16*>(sm + D2_AL);
    float* ST = reinterpret_cast<float*>(sm + D2_ST);
    __shared__ float b2s[144];

    int t = threadIdx.x;
    for (int i = t; i < 128 * 144; i += 256) {
        int k = i / 144, n = i - k * 144;
        WH[k * D2_LDW + n] = g_W2h[i];
        WL[k * D2_LDW + n] = g_W2l[i];
    }
    if (t < 144) b2s[t] = b2[t];

    int w = t >> 5;
    int m0 = (w & 3) * 16;
    int nh = w >> 2;
    int nfr = nh ? 4 : 5;
    int nbase = nh ? 80 : 0;

    const int ntiles = NEg / 64;
    for (int tile = blockIdx.x; tile < ntiles; tile += gridDim.x) {
        int eb = tile * 64;
        __syncthreads();
        for (int cid = t; cid < 64 * 32; cid += 256) {
            int e = cid >> 5, q = cid & 31;
            int k0 = q * 4;
            float4 v = *reinterpret_cast<const float4*>(g_hid + (size_t)(eb + e) * 128 + k0);
            __nv_bfloat16 h0 = __float2bfloat16(v.x), h1 = __float2bfloat16(v.y);
            __nv_bfloat16 h2 = __float2bfloat16(v.z), h3 = __float2bfloat16(v.w);
            __nv_bfloat16 l0 = __float2bfloat16(v.x - __bfloat162float(h0));
            __nv_bfloat16 l1 = __float2bfloat16(v.y - __bfloat162float(h1));
            __nv_bfloat16 l2 = __float2bfloat16(v.z - __bfloat162float(h2));
            __nv_bfloat16 l3 = __float2bfloat16(v.w - __bfloat162float(h3));
            int off = e * D2_LDA + k0;
            *reinterpret_cast<__nv_bfloat162*>(AH + off)     = __nv_bfloat162(h0, h1);
            *reinterpret_cast<__nv_bfloat162*>(AH + off + 2) = __nv_bfloat162(h2, h3);
            *reinterpret_cast<__nv_bfloat162*>(AL + off)     = __nv_bfloat162(l0, l1);
            *reinterpret_cast<__nv_bfloat162*>(AL + off + 2) = __nv_bfloat162(l2, l3);
        }
        __syncthreads();

        wmma::fragment<wmma::accumulator, 16, 16, 16, float> acc[5];
        for (int ni = 0; ni < 5; ni++) wmma::fill_fragment(acc[ni], 0.0f);

        for (int ks = 0; ks < 8; ks++) {
            wmma::fragment<wmma::matrix_a, 16, 16, 16, __nv_bfloat16, wmma::row_major> ah, al;
            wmma::load_matrix_sync(ah, AH + m0 * D2_LDA + ks * 16, D2_LDA);
            wmma::load_matrix_sync(al, AL + m0 * D2_LDA + ks * 16, D2_LDA);
            for (int ni = 0; ni < nfr; ni++) {
                int n0 = nbase + ni * 16;
                wmma::fragment<wmma::matrix_b, 16, 16, 16, __nv_bfloat16, wmma::row_major> bh, bl;
                wmma::load_matrix_sync(bh, WH + (ks * 16) * D2_LDW + n0, D2_LDW);
                wmma::load_matrix_sync(bl, WL + (ks * 16) * D2_LDW + n0, D2_LDW);
                wmma::mma_sync(acc[ni], ah, bh, acc[ni]);
                wmma::mma_sync(acc[ni], ah, bl, acc[ni]);
                wmma::mma_sync(acc[ni], al, bh, acc[ni]);
            }
        }
        __syncthreads();
        for (int ni = 0; ni < nfr; ni++)
            wmma::store_matrix_sync(ST + m0 * 144 + nbase + ni * 16,
                                    acc[ni], 144, wmma::mem_row_major);
        __syncthreads();
        for (int cid = t; cid < 64 * 36; cid += 256) {
            int e = cid / 36, cq = cid - e * 36;
            int c = cq * 4;
            float4 v = *reinterpret_cast<const float4*>(ST + e * 144 + c);
            float4 o;
            o.x = v.x + b2s[c + 0];
            o.y = v.y + b2s[c + 1];
            o.z = v.z + b2s[c + 2];
            o.w = v.w + b2s[c + 3];
            *reinterpret_cast<float4*>(out + (size_t)(eb + e) * 144 + c) = o;
        }
    }
}

// ---------------------------------------------------------------------------
extern "C" void kernel_launch(void* const* d_in, const int* in_sizes, int n_in,
                              void* d_out, int out_size) {
    const float* atom_fea = (const float*)d_in[0];
    const float* edge_fea = (const float*)d_in[1];
    const int*   sai      = (const int*)  d_in[2];
    const int*   sei      = (const int*)  d_in[3];
    const float* ang      = (const float*)d_in[4];
    const int*   sidx     = (const int*)  d_in[5];
    const float* dist     = (const float*)d_in[6];
    const float* Wf       = (const float*)d_in[7];
    const float* bf       = (const float*)d_in[8];
    const float* Ws       = (const float*)d_in[9];
    const float* bs       = (const float*)d_in[10];
    const float* W1       = (const float*)d_in[11];
    const float* b1       = (const float*)d_in[12];
    const float* W2       = (const float*)d_in[13];
    const float* b2       = (const float*)d_in[14];
    float* out = (float*)d_out;

    static bool attr_done = false;
    if (!attr_done) {
        cudaFuncSetAttribute(kBw,  cudaFuncAttributeMaxDynamicSharedMemorySize, B_SMEM);
        cudaFuncSetAttribute(kD1w, cudaFuncAttributeMaxDynamicSharedMemorySize, D1_SMEM);
        cudaFuncSetAttribute(kD2w, cudaFuncAttributeMaxDynamicSharedMemorySize, D2_SMEM);
        attr_done = true;
    }

    {
        size_t n4 = (size_t)2 * NEg * 64 / 4;
        int blocks = (int)((n4 + 255) / 256);
        kZero<<<blocks, 256>>>();
    }
    kW<<<248, 256>>>(W1, W2, Wf, Ws);
    kA<<<(NA + 31) / 32, 256>>>(atom_fea, Wf, Ws);
    kBw<<<148, 256, B_SMEM>>>(edge_fea);
    kC<<<2048, 256>>>(sai, sei, ang, sidx, dist, Wf, bf, Ws, bs);
    kD1w<<<148, 256, D1_SMEM>>>(edge_fea, b1);
    kD2w<<<148, 256, D2_SMEM>>>(b2, out);
}